// round 2
// baseline (speedup 1.0000x reference)
#include <cuda_runtime.h>
#include <math.h>

#define NROWS 16384
#define DDIM  2048
#define HDIM  512
#define CDIM  65

// ---------------- scratch (device globals; no allocation) ----------------
__device__ float         g_h[NROWS * HDIM];        // post-dropout hidden
__device__ unsigned char g_keep[NROWS * HDIM];     // dropout mask
__device__ float         g_logits[NROWS * CDIM];
__device__ float         g_lse[NROWS];
__device__ int           g_pred[NROWS];
__device__ float         g_sump[CDIM];
__device__ float         g_ent;
__device__ float         g_ce;
__device__ float         g_csum[CDIM * DDIM];
__device__ int           g_cnt[CDIM];
__device__ float         g_centT[DDIM * CDIM];     // [D][C] transposed centroids

// ---------------- threefry2x32 (JAX, key = (0, 42)) ----------------
__device__ __forceinline__ void threefry2x32_42(unsigned c0, unsigned c1,
                                                unsigned& o0, unsigned& o1)
{
    const unsigned ks0 = 0u;
    const unsigned ks1 = 42u;
    const unsigned ks2 = 0x1BD11BDAu ^ 0u ^ 42u;
    unsigned x0 = c0 + ks0;
    unsigned x1 = c1 + ks1;
#define TF_ROUND(r) { x0 += x1; x1 = (x1 << (r)) | (x1 >> (32 - (r))); x1 ^= x0; }
    TF_ROUND(13) TF_ROUND(15) TF_ROUND(26) TF_ROUND(6)
    x0 += ks1; x1 += ks2 + 1u;
    TF_ROUND(17) TF_ROUND(29) TF_ROUND(16) TF_ROUND(24)
    x0 += ks2; x1 += ks0 + 2u;
    TF_ROUND(13) TF_ROUND(15) TF_ROUND(26) TF_ROUND(6)
    x0 += ks0; x1 += ks1 + 3u;
    TF_ROUND(17) TF_ROUND(29) TF_ROUND(16) TF_ROUND(24)
    x0 += ks1; x1 += ks2 + 4u;
    TF_ROUND(13) TF_ROUND(15) TF_ROUND(26) TF_ROUND(6)
    x0 += ks2; x1 += ks0 + 5u;
#undef TF_ROUND
    o0 = x0; o1 = x1;
}

// JAX partitionable threefry (default since jax>=0.4.36):
// bits64[i] = (x0 << 32) | x1 with counters (hi32(i), lo32(i)) = (0, i);
// 32-bit bits = truncation = x1.  keep <=> uniform < 0.5 <=> top bit == 0.
__global__ void mask_kernel()
{
    int i = blockIdx.x * blockDim.x + threadIdx.x;
    if (i >= NROWS * HDIM) return;
    unsigned o0, o1;
    threefry2x32_42(0u, (unsigned)i, o0, o1);
    g_keep[i] = (unsigned char)((o1 >> 31) == 0u);
}

// ---------------- zero accumulators ----------------
__global__ void zero_kernel()
{
    int i = blockIdx.x * blockDim.x + threadIdx.x;
    if (i < CDIM * DDIM) g_csum[i] = 0.f;
    if (i < CDIM) { g_sump[i] = 0.f; g_cnt[i] = 0; }
    if (i == 0) { g_ent = 0.f; g_ce = 0.f; }
}

// ---------------- GEMM1: g_h = dropout(relu(feat @ w1 + b1)) ----------------
// 128x128 tile, BK=16, 256 threads, 8x8 per thread.
__global__ void __launch_bounds__(256) gemm1_kernel(const float* __restrict__ A,
                                                    const float* __restrict__ B,
                                                    const float* __restrict__ bias)
{
    __shared__ float As[16][128];   // transposed A tile
    __shared__ float Bs[16][128];
    const int tid  = threadIdx.x;
    const int brow = blockIdx.y * 128;
    const int bcol = blockIdx.x * 128;

    const int aRow = tid >> 2;           // 0..63
    const int aCol = (tid & 3) << 2;     // 0,4,8,12
    const int bRow = tid >> 5;           // 0..7
    const int bCol = (tid & 31) << 2;    // 0..124

    const int tRow = (tid >> 4) << 3;
    const int tCol = (tid & 15) << 3;

    float acc[8][8];
#pragma unroll
    for (int i = 0; i < 8; i++)
#pragma unroll
        for (int j = 0; j < 8; j++) acc[i][j] = 0.f;

    for (int k0 = 0; k0 < DDIM; k0 += 16) {
#pragma unroll
        for (int p = 0; p < 2; p++) {
            int r = aRow + p * 64;
            float4 v = *reinterpret_cast<const float4*>(&A[(brow + r) * DDIM + k0 + aCol]);
            As[aCol + 0][r] = v.x;
            As[aCol + 1][r] = v.y;
            As[aCol + 2][r] = v.z;
            As[aCol + 3][r] = v.w;
        }
#pragma unroll
        for (int p = 0; p < 2; p++) {
            int r = bRow + p * 8;
            *reinterpret_cast<float4*>(&Bs[r][bCol]) =
                *reinterpret_cast<const float4*>(&B[(k0 + r) * HDIM + bcol + bCol]);
        }
        __syncthreads();
#pragma unroll
        for (int k = 0; k < 16; k++) {
            float ra[8], rb[8];
            *reinterpret_cast<float4*>(ra)     = *reinterpret_cast<float4*>(&As[k][tRow]);
            *reinterpret_cast<float4*>(ra + 4) = *reinterpret_cast<float4*>(&As[k][tRow + 4]);
            *reinterpret_cast<float4*>(rb)     = *reinterpret_cast<float4*>(&Bs[k][tCol]);
            *reinterpret_cast<float4*>(rb + 4) = *reinterpret_cast<float4*>(&Bs[k][tCol + 4]);
#pragma unroll
            for (int i = 0; i < 8; i++)
#pragma unroll
                for (int j = 0; j < 8; j++)
                    acc[i][j] = fmaf(ra[i], rb[j], acc[i][j]);
        }
        __syncthreads();
    }

#pragma unroll
    for (int i = 0; i < 8; i++) {
        int gr = brow + tRow + i;
#pragma unroll
        for (int j = 0; j < 8; j++) {
            int gc  = bcol + tCol + j;
            float v = acc[i][j] + bias[gc];
            v = fmaxf(v, 0.f);
            int idx = gr * HDIM + gc;
            g_h[idx] = g_keep[idx] ? (v + v) : 0.f;
        }
    }
}

// ---------------- logits + softmax stats ----------------
// thread-per-row, 65 register accumulators, smem-tiled B.
__global__ void __launch_bounds__(128) logits_kernel(const float* __restrict__ W2,
                                                     const float* __restrict__ b2)
{
    __shared__ float sA[128][33];
    __shared__ float sB[32 * CDIM];
    __shared__ float ssump[CDIM];
    const int t    = threadIdx.x;
    const int row0 = blockIdx.x * 128;
    const int row  = row0 + t;

    float acc[CDIM];
#pragma unroll
    for (int j = 0; j < CDIM; j++) acc[j] = b2[j];

    for (int k0 = 0; k0 < HDIM; k0 += 32) {
#pragma unroll
        for (int p = 0; p < 8; p++) {
            int r = (t >> 3) + p * 16;
            int c = (t & 7) << 2;
            float4 v = *reinterpret_cast<const float4*>(&g_h[(row0 + r) * HDIM + k0 + c]);
            sA[r][c + 0] = v.x; sA[r][c + 1] = v.y; sA[r][c + 2] = v.z; sA[r][c + 3] = v.w;
        }
        for (int idx = t; idx < 32 * CDIM; idx += 128)
            sB[idx] = W2[k0 * CDIM + idx];
        __syncthreads();
#pragma unroll 4
        for (int k = 0; k < 32; k++) {
            float a = sA[t][k];
#pragma unroll
            for (int j = 0; j < CDIM; j++)
                acc[j] = fmaf(a, sB[k * CDIM + j], acc[j]);
        }
        __syncthreads();
    }

    // softmax stats / argmax / entropy
    float m = acc[0];
#pragma unroll
    for (int j = 1; j < CDIM; j++) m = fmaxf(m, acc[j]);
    float s = 0.f;
#pragma unroll
    for (int j = 0; j < CDIM; j++) s += expf(acc[j] - m);
    float lse = m + logf(s);

    if (t < CDIM) ssump[t] = 0.f;
    __syncthreads();

    float ent = 0.f;
    float bv = acc[0];
    int   bi = 0;
#pragma unroll
    for (int j = 0; j < CDIM; j++) {
        float p = expf(acc[j] - lse);
        ent += p * logf(p + 1e-6f);
        atomicAdd(&ssump[j], p);
        if (acc[j] > bv) { bv = acc[j]; bi = j; }
        g_logits[row * CDIM + j] = acc[j];
    }
    g_lse[row]  = lse;
    g_pred[row] = bi;

#pragma unroll
    for (int o = 16; o > 0; o >>= 1) ent += __shfl_down_sync(0xffffffffu, ent, o);
    if ((t & 31) == 0) atomicAdd(&g_ent, ent);

    __syncthreads();
    if (t < CDIM) atomicAdd(&g_sump[t], ssump[t]);
}

// ---------------- per-class segment sum over feat ----------------
// block: 128 columns; conflict-free per-thread smem accumulators, no inner atomics.
__global__ void __launch_bounds__(128) segsum_kernel(const float* __restrict__ feat)
{
    __shared__ float acc[CDIM * 128];   // 33.3 KB
    const int t   = threadIdx.x;
    const int col = blockIdx.x * 128 + t;
    const int rpb = NROWS / 16;                 // 1024 rows per block
    const int r0  = blockIdx.y * rpb;

    for (int i = t; i < CDIM * 128; i += 128) acc[i] = 0.f;
    __syncthreads();

    for (int i = r0; i < r0 + rpb; i++) {
        int cls = g_pred[i];
        acc[cls * 128 + t] += feat[i * DDIM + col];
    }
    __syncthreads();

    for (int c = 0; c < CDIM; c++)
        atomicAdd(&g_csum[c * DDIM + col], acc[c * 128 + t]);
}

__global__ void __launch_bounds__(512) count_kernel()
{
    __shared__ int h[CDIM];
    int t = threadIdx.x;
    if (t < CDIM) h[t] = 0;
    __syncthreads();
    int i = blockIdx.x * 512 + t;
    if (i < NROWS) atomicAdd(&h[g_pred[i]], 1);
    __syncthreads();
    if (t < CDIM) atomicAdd(&g_cnt[t], h[t]);
}

// ---------------- finalize centroids (normalized, transposed) ----------------
__global__ void __launch_bounds__(256) centroid_kernel()
{
    __shared__ float red[256];
    const int c = blockIdx.x;
    const int t = threadIdx.x;
    const int cnt = g_cnt[c];
    const float denom = fmaxf((float)cnt, 1.f);

    float ssq = 0.f;
    for (int d = t; d < DDIM; d += 256) {
        float mv = g_csum[c * DDIM + d] / denom;
        ssq += mv * mv;
    }
    red[t] = ssq;
    __syncthreads();
    for (int o = 128; o > 0; o >>= 1) { if (t < o) red[t] += red[t + o]; __syncthreads(); }
    float nrm   = sqrtf(red[0]);
    float scale = (cnt > 0) ? 1.f / (denom * fmaxf(nrm, 1e-12f)) : 0.f;

    for (int d = t; d < DDIM; d += 256)
        g_centT[d * CDIM + c] = g_csum[c * DDIM + d] * scale;
}

// ---------------- similarity argmax + CE ----------------
// argmax_j (feat_i . centroid_j) == argmax of normalized sim (row norm > 0 scalar).
__global__ void __launch_bounds__(128) sim_kernel(const float* __restrict__ feat)
{
    __shared__ float sA[128][33];
    __shared__ float sB[32 * CDIM];
    const int t    = threadIdx.x;
    const int row0 = blockIdx.x * 128;
    const int row  = row0 + t;

    float acc[CDIM];
#pragma unroll
    for (int j = 0; j < CDIM; j++) acc[j] = 0.f;

    for (int k0 = 0; k0 < DDIM; k0 += 32) {
#pragma unroll
        for (int p = 0; p < 8; p++) {
            int r = (t >> 3) + p * 16;
            int c = (t & 7) << 2;
            float4 v = *reinterpret_cast<const float4*>(&feat[(row0 + r) * DDIM + k0 + c]);
            sA[r][c + 0] = v.x; sA[r][c + 1] = v.y; sA[r][c + 2] = v.z; sA[r][c + 3] = v.w;
        }
        for (int idx = t; idx < 32 * CDIM; idx += 128)
            sB[idx] = g_centT[k0 * CDIM + idx];
        __syncthreads();
#pragma unroll 4
        for (int k = 0; k < 32; k++) {
            float a = sA[t][k];
#pragma unroll
            for (int j = 0; j < CDIM; j++)
                acc[j] = fmaf(a, sB[k * CDIM + j], acc[j]);
        }
        __syncthreads();
    }

    float bv = acc[0];
    int   bi = 0;
#pragma unroll
    for (int j = 1; j < CDIM; j++)
        if (acc[j] > bv) { bv = acc[j]; bi = j; }

    float term = g_lse[row] - g_logits[row * CDIM + bi];   // -logp[row, label]
#pragma unroll
    for (int o = 16; o > 0; o >>= 1) term += __shfl_down_sync(0xffffffffu, term, o);
    if ((t & 31) == 0) atomicAdd(&g_ce, term);
}

// ---------------- final scalar ----------------
__global__ void finalize_kernel(float* __restrict__ out)
{
    __shared__ float red[128];
    int t = threadIdx.x;
    float v = 0.f;
    if (t < CDIM) {
        float mp = g_sump[t] * (1.f / NROWS);
        v = mp * logf(mp + 1e-6f);
    }
    red[t] = v;
    __syncthreads();
    for (int o = 64; o > 0; o >>= 1) { if (t < o) red[t] += red[t + o]; __syncthreads(); }
    if (t == 0) {
        float entropy = -g_ent * (1.f / NROWS);
        float ce      =  g_ce  * (1.f / NROWS);
        out[0] = entropy + red[0] + 0.3f * ce;
    }
}

// ---------------- launch ----------------
extern "C" void kernel_launch(void* const* d_in, const int* in_sizes, int n_in,
                              void* d_out, int out_size)
{
    const float* feat = (const float*)d_in[0];
    const float* w1   = (const float*)d_in[1];
    const float* b1   = (const float*)d_in[2];
    const float* w2   = (const float*)d_in[3];
    const float* b2   = (const float*)d_in[4];
    float* out = (float*)d_out;

    zero_kernel<<<(CDIM * DDIM + 255) / 256, 256>>>();
    mask_kernel<<<(NROWS * HDIM + 255) / 256, 256>>>();
    gemm1_kernel<<<dim3(HDIM / 128, NROWS / 128), 256>>>(feat, w1, b1);
    logits_kernel<<<NROWS / 128, 128>>>(w2, b2);
    segsum_kernel<<<dim3(DDIM / 128, 16), 128>>>(feat);
    count_kernel<<<NROWS / 512, 512>>>();
    centroid_kernel<<<CDIM, 256>>>();
    sim_kernel<<<NROWS / 128, 128>>>(feat);
    finalize_kernel<<<1, 128>>>(out);
}

// round 3
// speedup vs baseline: 1.3063x; 1.3063x over previous
#include <cuda_runtime.h>
#include <math.h>

#define NROWS 16384
#define DDIM  2048
#define HDIM  512
#define CDIM  65

// ---------------- scratch (device globals; no allocation) ----------------
__device__ float         g_h[NROWS * HDIM];        // post-dropout hidden
__device__ unsigned char g_keep[NROWS * HDIM];     // dropout mask
__device__ float         g_logits[NROWS * CDIM];
__device__ float         g_lse[NROWS];
__device__ int           g_pred[NROWS];
__device__ float         g_sump[CDIM];
__device__ float         g_ent;
__device__ float         g_ce;
__device__ float         g_csum[CDIM * DDIM];
__device__ int           g_cnt[CDIM];
__device__ float         g_centT[DDIM * CDIM];     // [D][C] transposed centroids

// ---------------- threefry2x32 (JAX partitionable, key = (0, 42)) ----------------
__device__ __forceinline__ void threefry2x32_42(unsigned c0, unsigned c1,
                                                unsigned& o0, unsigned& o1)
{
    const unsigned ks0 = 0u;
    const unsigned ks1 = 42u;
    const unsigned ks2 = 0x1BD11BDAu ^ 0u ^ 42u;
    unsigned x0 = c0 + ks0;
    unsigned x1 = c1 + ks1;
#define TF_ROUND(r) { x0 += x1; x1 = (x1 << (r)) | (x1 >> (32 - (r))); x1 ^= x0; }
    TF_ROUND(13) TF_ROUND(15) TF_ROUND(26) TF_ROUND(6)
    x0 += ks1; x1 += ks2 + 1u;
    TF_ROUND(17) TF_ROUND(29) TF_ROUND(16) TF_ROUND(24)
    x0 += ks2; x1 += ks0 + 2u;
    TF_ROUND(13) TF_ROUND(15) TF_ROUND(26) TF_ROUND(6)
    x0 += ks0; x1 += ks1 + 3u;
    TF_ROUND(17) TF_ROUND(29) TF_ROUND(16) TF_ROUND(24)
    x0 += ks1; x1 += ks2 + 4u;
    TF_ROUND(13) TF_ROUND(15) TF_ROUND(26) TF_ROUND(6)
    x0 += ks2; x1 += ks0 + 5u;
#undef TF_ROUND
    o0 = x0; o1 = x1;
}

__global__ void mask_kernel()
{
    int i = blockIdx.x * blockDim.x + threadIdx.x;
    if (i >= NROWS * HDIM) return;
    unsigned o0, o1;
    threefry2x32_42(0u, (unsigned)i, o0, o1);
    g_keep[i] = (unsigned char)((o1 >> 31) == 0u);
}

__global__ void zero_kernel()
{
    int i = blockIdx.x * blockDim.x + threadIdx.x;
    if (i < CDIM * DDIM) g_csum[i] = 0.f;
    if (i < CDIM) { g_sump[i] = 0.f; g_cnt[i] = 0; }
    if (i == 0) { g_ent = 0.f; g_ce = 0.f; }
}

// ---------------- GEMM1: g_h = dropout(relu(feat @ w1 + b1)) ----------------
// 128x128 tile, BK=16, 256 threads, 8x8 per thread, double-buffered smem.
__global__ void __launch_bounds__(256) gemm1_kernel(const float* __restrict__ A,
                                                    const float* __restrict__ B,
                                                    const float* __restrict__ bias)
{
    __shared__ float As[2][16][128];
    __shared__ float Bs[2][16][128];
    const int tid  = threadIdx.x;
    const int brow = blockIdx.y * 128;
    const int bcol = blockIdx.x * 128;

    const int aRow = tid >> 2;           // 0..63
    const int aCol = (tid & 3) << 2;     // 0,4,8,12
    const int bRow = tid >> 5;           // 0..7
    const int bCol = (tid & 31) << 2;    // 0..124

    const int tRow = (tid >> 4) << 3;
    const int tCol = (tid & 15) << 3;

    float acc[8][8];
#pragma unroll
    for (int i = 0; i < 8; i++)
#pragma unroll
        for (int j = 0; j < 8; j++) acc[i][j] = 0.f;

    // prologue: load tile 0 into buffer 0
    float4 a0 = *reinterpret_cast<const float4*>(&A[(size_t)(brow + aRow) * DDIM + aCol]);
    float4 a1 = *reinterpret_cast<const float4*>(&A[(size_t)(brow + aRow + 64) * DDIM + aCol]);
    float4 b0 = *reinterpret_cast<const float4*>(&B[(size_t)bRow * HDIM + bcol + bCol]);
    float4 b1 = *reinterpret_cast<const float4*>(&B[(size_t)(bRow + 8) * HDIM + bcol + bCol]);
    As[0][aCol + 0][aRow] = a0.x; As[0][aCol + 1][aRow] = a0.y;
    As[0][aCol + 2][aRow] = a0.z; As[0][aCol + 3][aRow] = a0.w;
    As[0][aCol + 0][aRow + 64] = a1.x; As[0][aCol + 1][aRow + 64] = a1.y;
    As[0][aCol + 2][aRow + 64] = a1.z; As[0][aCol + 3][aRow + 64] = a1.w;
    *reinterpret_cast<float4*>(&Bs[0][bRow][bCol])     = b0;
    *reinterpret_cast<float4*>(&Bs[0][bRow + 8][bCol]) = b1;
    __syncthreads();

    int cur = 0;
    const int NT = DDIM / 16;    // 128
    for (int kt = 0; kt < NT; kt++) {
        const bool has = (kt + 1 < NT);
        if (has) {
            int k0n = (kt + 1) * 16;
            a0 = *reinterpret_cast<const float4*>(&A[(size_t)(brow + aRow) * DDIM + k0n + aCol]);
            a1 = *reinterpret_cast<const float4*>(&A[(size_t)(brow + aRow + 64) * DDIM + k0n + aCol]);
            b0 = *reinterpret_cast<const float4*>(&B[(size_t)(k0n + bRow) * HDIM + bcol + bCol]);
            b1 = *reinterpret_cast<const float4*>(&B[(size_t)(k0n + bRow + 8) * HDIM + bcol + bCol]);
        }
#pragma unroll
        for (int k = 0; k < 16; k++) {
            float ra[8], rb[8];
            *reinterpret_cast<float4*>(ra)     = *reinterpret_cast<float4*>(&As[cur][k][tRow]);
            *reinterpret_cast<float4*>(ra + 4) = *reinterpret_cast<float4*>(&As[cur][k][tRow + 4]);
            *reinterpret_cast<float4*>(rb)     = *reinterpret_cast<float4*>(&Bs[cur][k][tCol]);
            *reinterpret_cast<float4*>(rb + 4) = *reinterpret_cast<float4*>(&Bs[cur][k][tCol + 4]);
#pragma unroll
            for (int i = 0; i < 8; i++)
#pragma unroll
                for (int j = 0; j < 8; j++)
                    acc[i][j] = fmaf(ra[i], rb[j], acc[i][j]);
        }
        if (has) {
            int nxt = cur ^ 1;
            As[nxt][aCol + 0][aRow] = a0.x; As[nxt][aCol + 1][aRow] = a0.y;
            As[nxt][aCol + 2][aRow] = a0.z; As[nxt][aCol + 3][aRow] = a0.w;
            As[nxt][aCol + 0][aRow + 64] = a1.x; As[nxt][aCol + 1][aRow + 64] = a1.y;
            As[nxt][aCol + 2][aRow + 64] = a1.z; As[nxt][aCol + 3][aRow + 64] = a1.w;
            *reinterpret_cast<float4*>(&Bs[nxt][bRow][bCol])     = b0;
            *reinterpret_cast<float4*>(&Bs[nxt][bRow + 8][bCol]) = b1;
            __syncthreads();
            cur = nxt;
        }
    }

#pragma unroll
    for (int i = 0; i < 8; i++) {
        int gr = brow + tRow + i;
#pragma unroll
        for (int j = 0; j < 8; j++) {
            int gc  = bcol + tCol + j;
            float v = acc[i][j] + bias[gc];
            v = fmaxf(v, 0.f);
            int idx = gr * HDIM + gc;
            g_h[idx] = g_keep[idx] ? (v + v) : 0.f;
        }
    }
}

// ============================================================================
// Tiled skinny GEMM building block: 32 rows x 65 cols per block, 128 threads.
// tr = tid&7 (4 rows each), tc = tid>>3 (4 cols each); tc==0 also owns col 64.
// ============================================================================

// ---------------- logits + softmax stats + counts ----------------
__global__ void __launch_bounds__(128) logits_kernel(const float* __restrict__ W2,
                                                     const float* __restrict__ b2)
{
    __shared__ __align__(16) float buf[3200];   // sA[32][32] | sB[32][68] ; reused as sOut[32][68]
    __shared__ float ssump[CDIM];
    __shared__ int   scnt[CDIM];
    __shared__ float s_ent;
    float (*sA)[32] = reinterpret_cast<float(*)[32]>(buf);
    float (*sB)[68] = reinterpret_cast<float(*)[68]>(buf + 1024);
    float (*sOut)[68] = reinterpret_cast<float(*)[68]>(buf);

    const int tid  = threadIdx.x;
    const int lane = tid & 31;
    const int w    = tid >> 5;
    const int tr   = tid & 7;
    const int tc   = tid >> 3;
    const int row0 = blockIdx.x * 32;

    if (tid < CDIM) { ssump[tid] = 0.f; scnt[tid] = 0; }
    if (tid == 0) s_ent = 0.f;

    float acc[4][4];
#pragma unroll
    for (int i = 0; i < 4; i++)
#pragma unroll
        for (int j = 0; j < 4; j++) acc[i][j] = 0.f;
    float acc64[4] = {0.f, 0.f, 0.f, 0.f};

    const int lr = tid & 31;            // loader row 0..31
    const int lc = (tid >> 5) * 8;      // loader col 0,8,16,24
    const float* arow = &g_h[(size_t)(row0 + lr) * HDIM + lc];

    for (int kt = 0; kt < HDIM / 32; kt++) {
        float4 x0 = *reinterpret_cast<const float4*>(arow + kt * 32);
        float4 x1 = *reinterpret_cast<const float4*>(arow + kt * 32 + 4);
        sA[lc + 0][lr] = x0.x; sA[lc + 1][lr] = x0.y; sA[lc + 2][lr] = x0.z; sA[lc + 3][lr] = x0.w;
        sA[lc + 4][lr] = x1.x; sA[lc + 5][lr] = x1.y; sA[lc + 6][lr] = x1.z; sA[lc + 7][lr] = x1.w;
        for (int i = tid; i < 32 * CDIM; i += 128) {
            int kk = i / CDIM;
            sB[kk][i - kk * CDIM] = W2[(kt * 32 + kk) * CDIM + (i - kk * CDIM)];
        }
        __syncthreads();
#pragma unroll
        for (int k = 0; k < 32; k++) {
            float4 ra = *reinterpret_cast<float4*>(&sA[k][tr * 4]);
            float4 rb = *reinterpret_cast<float4*>(&sB[k][tc * 4]);
            float a[4] = {ra.x, ra.y, ra.z, ra.w};
            float b[4] = {rb.x, rb.y, rb.z, rb.w};
#pragma unroll
            for (int i = 0; i < 4; i++)
#pragma unroll
                for (int j = 0; j < 4; j++)
                    acc[i][j] = fmaf(a[i], b[j], acc[i][j]);
            if (tc == 0) {
                float b64 = sB[k][64];
#pragma unroll
                for (int i = 0; i < 4; i++) acc64[i] = fmaf(a[i], b64, acc64[i]);
            }
        }
        __syncthreads();
    }

    // write logits (with bias) to staging tile
    float bj[4];
#pragma unroll
    for (int j = 0; j < 4; j++) bj[j] = b2[tc * 4 + j];
#pragma unroll
    for (int i = 0; i < 4; i++)
#pragma unroll
        for (int j = 0; j < 4; j++)
            sOut[tr * 4 + i][tc * 4 + j] = acc[i][j] + bj[j];
    if (tc == 0) {
        float b64b = b2[64];
#pragma unroll
        for (int i = 0; i < 4; i++) sOut[tr * 4 + i][64] = acc64[i] + b64b;
    }
    __syncthreads();

    // epilogue: warp w handles rows w*8..w*8+7
    float su0 = 0.f, su1 = 0.f, su2 = 0.f, entL = 0.f;
    for (int rr = 0; rr < 8; rr++) {
        int r   = w * 8 + rr;
        int row = row0 + r;
        float v0 = sOut[r][lane];
        float v1 = sOut[r][lane + 32];
        float v2 = sOut[r][64];

        float m = fmaxf(v0, v1);
#pragma unroll
        for (int o = 16; o > 0; o >>= 1) m = fmaxf(m, __shfl_xor_sync(0xffffffffu, m, o));
        m = fmaxf(m, v2);

        float s = expf(v0 - m) + expf(v1 - m);
#pragma unroll
        for (int o = 16; o > 0; o >>= 1) s += __shfl_xor_sync(0xffffffffu, s, o);
        s += expf(v2 - m);
        float lse = m + logf(s);

        float p0 = expf(v0 - lse), p1 = expf(v1 - lse), p2 = expf(v2 - lse);
        entL += p0 * logf(p0 + 1e-6f) + p1 * logf(p1 + 1e-6f);
        su0 += p0; su1 += p1;
        if (lane == 0) { entL += p2 * logf(p2 + 1e-6f); su2 += p2; }

        // argmax (lowest index wins ties)
        float bv; int bi;
        if (v1 > v0) { bv = v1; bi = lane + 32; } else { bv = v0; bi = lane; }
#pragma unroll
        for (int o = 16; o > 0; o >>= 1) {
            float ov = __shfl_xor_sync(0xffffffffu, bv, o);
            int   oi = __shfl_xor_sync(0xffffffffu, bi, o);
            if (ov > bv || (ov == bv && oi < bi)) { bv = ov; bi = oi; }
        }
        if (v2 > bv) { bv = v2; bi = 64; }

        g_logits[row * CDIM + lane]      = v0;
        g_logits[row * CDIM + lane + 32] = v1;
        if (lane == 0) {
            g_logits[row * CDIM + 64] = v2;
            g_lse[row]  = lse;
            g_pred[row] = bi;
            atomicAdd(&scnt[bi], 1);
        }
    }
#pragma unroll
    for (int o = 16; o > 0; o >>= 1) entL += __shfl_xor_sync(0xffffffffu, entL, o);
    atomicAdd(&ssump[lane], su0);
    atomicAdd(&ssump[lane + 32], su1);
    if (lane == 0) { atomicAdd(&ssump[64], su2); atomicAdd(&s_ent, entL); }
    __syncthreads();
    if (tid < CDIM) {
        atomicAdd(&g_sump[tid], ssump[tid]);
        atomicAdd(&g_cnt[tid], scnt[tid]);
    }
    if (tid == 0) atomicAdd(&g_ent, s_ent);
}

// ---------------- per-class segment sum over feat ----------------
__global__ void __launch_bounds__(128) segsum_kernel(const float* __restrict__ feat)
{
    __shared__ float acc[CDIM * 128];   // 33.3 KB
    const int t   = threadIdx.x;
    const int col = blockIdx.x * 128 + t;
    const int rpb = NROWS / 16;
    const int r0  = blockIdx.y * rpb;

    for (int i = t; i < CDIM * 128; i += 128) acc[i] = 0.f;
    __syncthreads();

    for (int i = r0; i < r0 + rpb; i++) {
        int cls = g_pred[i];
        acc[cls * 128 + t] += feat[(size_t)i * DDIM + col];
    }
    __syncthreads();

    for (int c = 0; c < CDIM; c++)
        atomicAdd(&g_csum[c * DDIM + col], acc[c * 128 + t]);
}

// ---------------- finalize centroids (normalized, transposed) ----------------
__global__ void __launch_bounds__(256) centroid_kernel()
{
    __shared__ float red[256];
    const int c = blockIdx.x;
    const int t = threadIdx.x;
    const int cnt = g_cnt[c];
    const float denom = fmaxf((float)cnt, 1.f);

    float ssq = 0.f;
    for (int d = t; d < DDIM; d += 256) {
        float mv = g_csum[c * DDIM + d] / denom;
        ssq += mv * mv;
    }
    red[t] = ssq;
    __syncthreads();
    for (int o = 128; o > 0; o >>= 1) { if (t < o) red[t] += red[t + o]; __syncthreads(); }
    float nrm   = sqrtf(red[0]);
    float scale = (cnt > 0) ? 1.f / (denom * fmaxf(nrm, 1e-12f)) : 0.f;

    for (int d = t; d < DDIM; d += 256)
        g_centT[d * CDIM + c] = g_csum[c * DDIM + d] * scale;
}

// ---------------- similarity argmax + CE ----------------
__global__ void __launch_bounds__(128) sim_kernel(const float* __restrict__ feat)
{
    __shared__ __align__(16) float buf[3200];
    __shared__ float s_ce;
    float (*sA)[32] = reinterpret_cast<float(*)[32]>(buf);
    float (*sB)[68] = reinterpret_cast<float(*)[68]>(buf + 1024);
    float (*sOut)[68] = reinterpret_cast<float(*)[68]>(buf);

    const int tid  = threadIdx.x;
    const int lane = tid & 31;
    const int w    = tid >> 5;
    const int tr   = tid & 7;
    const int tc   = tid >> 3;
    const int row0 = blockIdx.x * 32;

    if (tid == 0) s_ce = 0.f;

    float acc[4][4];
#pragma unroll
    for (int i = 0; i < 4; i++)
#pragma unroll
        for (int j = 0; j < 4; j++) acc[i][j] = 0.f;
    float acc64[4] = {0.f, 0.f, 0.f, 0.f};

    const int lr = tid & 31;
    const int lc = (tid >> 5) * 8;
    const float* arow = &feat[(size_t)(row0 + lr) * DDIM + lc];

    for (int kt = 0; kt < DDIM / 32; kt++) {
        float4 x0 = *reinterpret_cast<const float4*>(arow + kt * 32);
        float4 x1 = *reinterpret_cast<const float4*>(arow + kt * 32 + 4);
        sA[lc + 0][lr] = x0.x; sA[lc + 1][lr] = x0.y; sA[lc + 2][lr] = x0.z; sA[lc + 3][lr] = x0.w;
        sA[lc + 4][lr] = x1.x; sA[lc + 5][lr] = x1.y; sA[lc + 6][lr] = x1.z; sA[lc + 7][lr] = x1.w;
        for (int i = tid; i < 32 * CDIM; i += 128) {
            int kk = i / CDIM;
            sB[kk][i - kk * CDIM] = g_centT[(kt * 32 + kk) * CDIM + (i - kk * CDIM)];
        }
        __syncthreads();
#pragma unroll
        for (int k = 0; k < 32; k++) {
            float4 ra = *reinterpret_cast<float4*>(&sA[k][tr * 4]);
            float4 rb = *reinterpret_cast<float4*>(&sB[k][tc * 4]);
            float a[4] = {ra.x, ra.y, ra.z, ra.w};
            float b[4] = {rb.x, rb.y, rb.z, rb.w};
#pragma unroll
            for (int i = 0; i < 4; i++)
#pragma unroll
                for (int j = 0; j < 4; j++)
                    acc[i][j] = fmaf(a[i], b[j], acc[i][j]);
            if (tc == 0) {
                float b64 = sB[k][64];
#pragma unroll
                for (int i = 0; i < 4; i++) acc64[i] = fmaf(a[i], b64, acc64[i]);
            }
        }
        __syncthreads();
    }

#pragma unroll
    for (int i = 0; i < 4; i++)
#pragma unroll
        for (int j = 0; j < 4; j++)
            sOut[tr * 4 + i][tc * 4 + j] = acc[i][j];
    if (tc == 0) {
#pragma unroll
        for (int i = 0; i < 4; i++) sOut[tr * 4 + i][64] = acc64[i];
    }
    __syncthreads();

    float ceL = 0.f;
    for (int rr = 0; rr < 8; rr++) {
        int r   = w * 8 + rr;
        int row = row0 + r;
        float v0 = sOut[r][lane];
        float v1 = sOut[r][lane + 32];
        float v2 = sOut[r][64];

        float bv; int bi;
        if (v1 > v0) { bv = v1; bi = lane + 32; } else { bv = v0; bi = lane; }
#pragma unroll
        for (int o = 16; o > 0; o >>= 1) {
            float ov = __shfl_xor_sync(0xffffffffu, bv, o);
            int   oi = __shfl_xor_sync(0xffffffffu, bi, o);
            if (ov > bv || (ov == bv && oi < bi)) { bv = ov; bi = oi; }
        }
        if (v2 > bv) { bv = v2; bi = 64; }

        if (lane == 0)
            ceL += g_lse[row] - g_logits[row * CDIM + bi];
    }
    if (lane == 0) atomicAdd(&s_ce, ceL);
    __syncthreads();
    if (tid == 0) atomicAdd(&g_ce, s_ce);
}

// ---------------- final scalar ----------------
__global__ void finalize_kernel(float* __restrict__ out)
{
    __shared__ float red[128];
    int t = threadIdx.x;
    float v = 0.f;
    if (t < CDIM) {
        float mp = g_sump[t] * (1.f / NROWS);
        v = mp * logf(mp + 1e-6f);
    }
    red[t] = v;
    __syncthreads();
    for (int o = 64; o > 0; o >>= 1) { if (t < o) red[t] += red[t + o]; __syncthreads(); }
    if (t == 0) {
        float entropy = -g_ent * (1.f / NROWS);
        float ce      =  g_ce  * (1.f / NROWS);
        out[0] = entropy + red[0] + 0.3f * ce;
    }
}

// ---------------- launch ----------------
extern "C" void kernel_launch(void* const* d_in, const int* in_sizes, int n_in,
                              void* d_out, int out_size)
{
    const float* feat = (const float*)d_in[0];
    const float* w1   = (const float*)d_in[1];
    const float* b1   = (const float*)d_in[2];
    const float* w2   = (const float*)d_in[3];
    const float* b2   = (const float*)d_in[4];
    float* out = (float*)d_out;

    zero_kernel<<<(CDIM * DDIM + 255) / 256, 256>>>();
    mask_kernel<<<(NROWS * HDIM + 255) / 256, 256>>>();
    gemm1_kernel<<<dim3(HDIM / 128, NROWS / 128), 256>>>(feat, w1, b1);
    logits_kernel<<<NROWS / 32, 128>>>(w2, b2);
    segsum_kernel<<<dim3(DDIM / 128, 16), 128>>>(feat);
    centroid_kernel<<<CDIM, 256>>>();
    sim_kernel<<<NROWS / 32, 128>>>(feat);
    finalize_kernel<<<1, 128>>>(out);
}

// round 4
// speedup vs baseline: 3.5638x; 2.7282x over previous
#include <cuda_runtime.h>
#include <math.h>

#define NROWS 16384
#define DDIM  2048
#define HDIM  512
#define CDIM  65
#define CPAD  72

// ---------------- scratch (device globals; no allocation) ----------------
__device__ float         g_h[NROWS * HDIM];        // post-dropout hidden (fp32)
__device__ unsigned char g_keep[NROWS * HDIM];     // dropout mask
__device__ float         g_logits[NROWS * CDIM];
__device__ float         g_lse[NROWS];
__device__ int           g_pred[NROWS];
__device__ float         g_sump[CDIM];
__device__ float         g_ent;
__device__ float         g_ce;
__device__ float         g_csum[CDIM * DDIM];
__device__ int           g_cnt[CDIM];
__device__ unsigned      g_w2p[HDIM * CPAD];       // tf32 bits, padded
__device__ unsigned      g_centTp[DDIM * CPAD];    // tf32 bits, padded, [D][CPAD]

// ---------------- tf32 helpers ----------------
__device__ __forceinline__ unsigned f2tf32(float x)
{
    unsigned u;
    asm("cvt.rna.tf32.f32 %0, %1;" : "=r"(u) : "f"(x));
    return u;
}

__device__ __forceinline__ void mma_tf32(float c[4],
                                         unsigned a0, unsigned a1, unsigned a2, unsigned a3,
                                         unsigned b0, unsigned b1)
{
    asm volatile(
        "mma.sync.aligned.m16n8k8.row.col.f32.tf32.tf32.f32 "
        "{%0,%1,%2,%3}, {%4,%5,%6,%7}, {%8,%9}, {%0,%1,%2,%3};"
        : "+f"(c[0]), "+f"(c[1]), "+f"(c[2]), "+f"(c[3])
        : "r"(a0), "r"(a1), "r"(a2), "r"(a3), "r"(b0), "r"(b1));
}

// ---------------- threefry2x32 (JAX partitionable, key = (0, 42)) ----------------
__device__ __forceinline__ void threefry2x32_42(unsigned c0, unsigned c1,
                                                unsigned& o0, unsigned& o1)
{
    const unsigned ks0 = 0u;
    const unsigned ks1 = 42u;
    const unsigned ks2 = 0x1BD11BDAu ^ 0u ^ 42u;
    unsigned x0 = c0 + ks0;
    unsigned x1 = c1 + ks1;
#define TF_ROUND(r) { x0 += x1; x1 = (x1 << (r)) | (x1 >> (32 - (r))); x1 ^= x0; }
    TF_ROUND(13) TF_ROUND(15) TF_ROUND(26) TF_ROUND(6)
    x0 += ks1; x1 += ks2 + 1u;
    TF_ROUND(17) TF_ROUND(29) TF_ROUND(16) TF_ROUND(24)
    x0 += ks2; x1 += ks0 + 2u;
    TF_ROUND(13) TF_ROUND(15) TF_ROUND(26) TF_ROUND(6)
    x0 += ks0; x1 += ks1 + 3u;
    TF_ROUND(17) TF_ROUND(29) TF_ROUND(16) TF_ROUND(24)
    x0 += ks1; x1 += ks2 + 4u;
    TF_ROUND(13) TF_ROUND(15) TF_ROUND(26) TF_ROUND(6)
    x0 += ks2; x1 += ks0 + 5u;
#undef TF_ROUND
    o0 = x0; o1 = x1;
}

__global__ void mask_kernel()
{
    int i = blockIdx.x * blockDim.x + threadIdx.x;
    if (i >= NROWS * HDIM) return;
    unsigned o0, o1;
    threefry2x32_42(0u, (unsigned)i, o0, o1);
    g_keep[i] = (unsigned char)((o1 >> 31) == 0u);
}

__global__ void zero_kernel()
{
    int i = blockIdx.x * blockDim.x + threadIdx.x;
    if (i < DDIM * CPAD) g_centTp[i] = 0u;
    if (i < CDIM * DDIM) g_csum[i] = 0.f;
    if (i < CDIM) { g_sump[i] = 0.f; g_cnt[i] = 0; }
    if (i == 0) { g_ent = 0.f; g_ce = 0.f; }
}

__global__ void pad_w2_kernel(const float* __restrict__ w2)
{
    int i = blockIdx.x * blockDim.x + threadIdx.x;
    if (i >= HDIM * CPAD) return;
    int row = i / CPAD, col = i - row * CPAD;
    g_w2p[i] = (col < CDIM) ? f2tf32(w2[row * CDIM + col]) : 0u;
}

// ============================================================================
// GEMM1 (TF32 TC): g_h = dropout(relu(feat @ w1 + b1))
// 128x128 block, BK=32, 256 threads, 8 warps of 64x32; reg-staged pipeline.
// ============================================================================
__global__ void __launch_bounds__(256) gemm1_tc(const float* __restrict__ A,
                                                const float* __restrict__ B,
                                                const float* __restrict__ bias)
{
    __shared__ unsigned As[128 * 36];   // [row][k], stride 36 (conflict-free frags)
    __shared__ unsigned Bs[32 * 136];   // [k][n],  stride 136

    const int tid  = threadIdx.x;
    const int lane = tid & 31;
    const int w    = tid >> 5;
    const int g    = lane >> 2;
    const int t    = lane & 3;
    const int wm   = w & 1;             // 0..1 (64 rows each)
    const int wn   = w >> 1;            // 0..3 (32 cols each)
    const int brow = blockIdx.y * 128;
    const int bcol = blockIdx.x * 128;

    const int ar = tid >> 3;            // 0..31
    const int af = (tid & 7) * 4;       // 0..28
    const int br = tid >> 5;            // 0..7
    const int bf = (tid & 31) * 4;      // 0..124

    float acc[4][4][4];
#pragma unroll
    for (int i = 0; i < 4; i++)
#pragma unroll
        for (int j = 0; j < 4; j++)
#pragma unroll
            for (int c = 0; c < 4; c++) acc[i][j][c] = 0.f;

    float4 asg[4], bsg[4];
    const int NT = DDIM / 32;           // 64

    // prologue load
#pragma unroll
    for (int p = 0; p < 4; p++) {
        asg[p] = *reinterpret_cast<const float4*>(&A[(size_t)(brow + ar + 32 * p) * DDIM + af]);
        bsg[p] = *reinterpret_cast<const float4*>(&B[(size_t)(br + 8 * p) * HDIM + bcol + bf]);
    }

    for (int kt = 0; kt < NT; kt++) {
        // store staged regs -> smem (cvt to tf32)
#pragma unroll
        for (int p = 0; p < 4; p++) {
            int rb = (ar + 32 * p) * 36 + af;
            As[rb + 0] = f2tf32(asg[p].x); As[rb + 1] = f2tf32(asg[p].y);
            As[rb + 2] = f2tf32(asg[p].z); As[rb + 3] = f2tf32(asg[p].w);
            int bb = (br + 8 * p) * 136 + bf;
            Bs[bb + 0] = f2tf32(bsg[p].x); Bs[bb + 1] = f2tf32(bsg[p].y);
            Bs[bb + 2] = f2tf32(bsg[p].z); Bs[bb + 3] = f2tf32(bsg[p].w);
        }
        __syncthreads();

        if (kt + 1 < NT) {
            int k0n = (kt + 1) * 32;
#pragma unroll
            for (int p = 0; p < 4; p++) {
                asg[p] = *reinterpret_cast<const float4*>(&A[(size_t)(brow + ar + 32 * p) * DDIM + k0n + af]);
                bsg[p] = *reinterpret_cast<const float4*>(&B[(size_t)(k0n + br + 8 * p) * HDIM + bcol + bf]);
            }
        }

#pragma unroll
        for (int ks = 0; ks < 4; ks++) {
            int k0 = ks * 8;
            unsigned afr[4][4];
#pragma unroll
            for (int mt = 0; mt < 4; mt++) {
                int row = wm * 64 + mt * 16;
                afr[mt][0] = As[(row + g) * 36 + k0 + t];
                afr[mt][1] = As[(row + 8 + g) * 36 + k0 + t];
                afr[mt][2] = As[(row + g) * 36 + k0 + t + 4];
                afr[mt][3] = As[(row + 8 + g) * 36 + k0 + t + 4];
            }
            unsigned bfr[4][2];
#pragma unroll
            for (int nt = 0; nt < 4; nt++) {
                int col = wn * 32 + nt * 8;
                bfr[nt][0] = Bs[(k0 + t) * 136 + col + g];
                bfr[nt][1] = Bs[(k0 + t + 4) * 136 + col + g];
            }
#pragma unroll
            for (int mt = 0; mt < 4; mt++)
#pragma unroll
                for (int nt = 0; nt < 4; nt++)
                    mma_tf32(acc[mt][nt], afr[mt][0], afr[mt][1], afr[mt][2], afr[mt][3],
                             bfr[nt][0], bfr[nt][1]);
        }
        __syncthreads();
    }

    // epilogue: bias + relu + dropout -> g_h
#pragma unroll
    for (int mt = 0; mt < 4; mt++) {
        int r0 = brow + wm * 64 + mt * 16 + g;
        int r1 = r0 + 8;
#pragma unroll
        for (int nt = 0; nt < 4; nt++) {
            int col0 = bcol + wn * 32 + nt * 8 + 2 * t;
            float b0 = bias[col0], b1 = bias[col0 + 1];

            {
                int idx = r0 * HDIM + col0;
                uchar2 kp = *reinterpret_cast<const uchar2*>(&g_keep[idx]);
                float v0 = fmaxf(acc[mt][nt][0] + b0, 0.f);
                float v1 = fmaxf(acc[mt][nt][1] + b1, 0.f);
                float2 o = make_float2(kp.x ? v0 + v0 : 0.f, kp.y ? v1 + v1 : 0.f);
                *reinterpret_cast<float2*>(&g_h[idx]) = o;
            }
            {
                int idx = r1 * HDIM + col0;
                uchar2 kp = *reinterpret_cast<const uchar2*>(&g_keep[idx]);
                float v0 = fmaxf(acc[mt][nt][2] + b0, 0.f);
                float v1 = fmaxf(acc[mt][nt][3] + b1, 0.f);
                float2 o = make_float2(kp.x ? v0 + v0 : 0.f, kp.y ? v1 + v1 : 0.f);
                *reinterpret_cast<float2*>(&g_h[idx]) = o;
            }
        }
    }
}

// ============================================================================
// logits (TF32 TC): logits = g_h @ w2p + b2; fused softmax stats/argmax/counts.
// 64 rows x 72 cols per block, 128 threads, 4 warps of 16 rows; BK=32.
// ============================================================================
__global__ void __launch_bounds__(128) logits_tc(const float* __restrict__ b2)
{
    __shared__ unsigned As[64 * 36];
    __shared__ unsigned Bs[32 * 76];

    const int tid  = threadIdx.x;
    const int lane = tid & 31;
    const int w    = tid >> 5;
    const int g    = lane >> 2;
    const int t    = lane & 3;
    const int row0 = blockIdx.x * 64;

    const int ar = tid >> 3;            // 0..15
    const int af = (tid & 7) * 4;

    int soff[18];
#pragma unroll
    for (int p = 0; p < 18; p++) {
        int i = tid + 128 * p;
        soff[p] = i + 4 * (i / CPAD);   // kk*76 + nn
    }

    float acc[9][4];
#pragma unroll
    for (int n = 0; n < 9; n++)
#pragma unroll
        for (int c = 0; c < 4; c++) acc[n][c] = 0.f;

    float4 asg[4];
    unsigned bsg[18];
    const int NT = HDIM / 32;           // 16

#pragma unroll
    for (int p = 0; p < 4; p++)
        asg[p] = *reinterpret_cast<const float4*>(&g_h[(size_t)(row0 + ar + 16 * p) * HDIM + af]);
#pragma unroll
    for (int p = 0; p < 18; p++)
        bsg[p] = g_w2p[tid + 128 * p];

    for (int kt = 0; kt < NT; kt++) {
#pragma unroll
        for (int p = 0; p < 4; p++) {
            int rb = (ar + 16 * p) * 36 + af;
            As[rb + 0] = f2tf32(asg[p].x); As[rb + 1] = f2tf32(asg[p].y);
            As[rb + 2] = f2tf32(asg[p].z); As[rb + 3] = f2tf32(asg[p].w);
        }
#pragma unroll
        for (int p = 0; p < 18; p++) Bs[soff[p]] = bsg[p];
        __syncthreads();

        if (kt + 1 < NT) {
            int k0n = (kt + 1) * 32;
#pragma unroll
            for (int p = 0; p < 4; p++)
                asg[p] = *reinterpret_cast<const float4*>(&g_h[(size_t)(row0 + ar + 16 * p) * HDIM + k0n + af]);
#pragma unroll
            for (int p = 0; p < 18; p++)
                bsg[p] = g_w2p[k0n * CPAD + tid + 128 * p];
        }

#pragma unroll
        for (int ks = 0; ks < 4; ks++) {
            int k0 = ks * 8;
            int row = w * 16;
            unsigned a0 = As[(row + g) * 36 + k0 + t];
            unsigned a1 = As[(row + 8 + g) * 36 + k0 + t];
            unsigned a2 = As[(row + g) * 36 + k0 + t + 4];
            unsigned a3 = As[(row + 8 + g) * 36 + k0 + t + 4];
#pragma unroll
            for (int nt = 0; nt < 9; nt++) {
                unsigned b0 = Bs[(k0 + t) * 76 + nt * 8 + g];
                unsigned b1 = Bs[(k0 + t + 4) * 76 + nt * 8 + g];
                mma_tf32(acc[nt], a0, a1, a2, a3, b0, b1);
            }
        }
        __syncthreads();
    }

    // ---- epilogue ----
    float su[9][2];
#pragma unroll
    for (int n = 0; n < 9; n++) { su[n][0] = 0.f; su[n][1] = 0.f; }
    float entL = 0.f;

#pragma unroll
    for (int half = 0; half < 2; half++) {
        int row = row0 + w * 16 + g + 8 * half;
        int ci  = 2 * half;

        float v[9][2];
        float m = -1e30f;
#pragma unroll
        for (int nt = 0; nt < 9; nt++)
#pragma unroll
            for (int j = 0; j < 2; j++) {
                int col = nt * 8 + 2 * t + j;
                v[nt][j] = (col < CDIM) ? acc[nt][ci + j] + b2[col] : -1e30f;
                m = fmaxf(m, v[nt][j]);
            }
        m = fmaxf(m, __shfl_xor_sync(0xffffffffu, m, 1));
        m = fmaxf(m, __shfl_xor_sync(0xffffffffu, m, 2));

        float s = 0.f;
#pragma unroll
        for (int nt = 0; nt < 9; nt++)
#pragma unroll
            for (int j = 0; j < 2; j++) {
                int col = nt * 8 + 2 * t + j;
                if (col < CDIM) s += expf(v[nt][j] - m);
            }
        s += __shfl_xor_sync(0xffffffffu, s, 1);
        s += __shfl_xor_sync(0xffffffffu, s, 2);
        float lse = m + logf(s);

        float bv = -1e30f; int bi = CDIM;
#pragma unroll
        for (int nt = 0; nt < 9; nt++)
#pragma unroll
            for (int j = 0; j < 2; j++) {
                int col = nt * 8 + 2 * t + j;
                if (col < CDIM) {
                    float p = expf(v[nt][j] - lse);
                    entL += p * logf(p + 1e-6f);
                    su[nt][j] += p;
                    g_logits[row * CDIM + col] = v[nt][j];
                    if (v[nt][j] > bv || (v[nt][j] == bv && col < bi)) { bv = v[nt][j]; bi = col; }
                }
            }
#pragma unroll
        for (int o = 1; o <= 2; o <<= 1) {
            float ov = __shfl_xor_sync(0xffffffffu, bv, o);
            int   oi = __shfl_xor_sync(0xffffffffu, bi, o);
            if (ov > bv || (ov == bv && oi < bi)) { bv = ov; bi = oi; }
        }
        if (t == 0) {
            g_lse[row]  = lse;
            g_pred[row] = bi;
            atomicAdd(&g_cnt[bi], 1);
        }
    }

#pragma unroll
    for (int o = 16; o > 0; o >>= 1) entL += __shfl_xor_sync(0xffffffffu, entL, o);
    if (lane == 0) atomicAdd(&g_ent, entL);

#pragma unroll
    for (int o = 4; o <= 16; o <<= 1)
#pragma unroll
        for (int nt = 0; nt < 9; nt++)
#pragma unroll
            for (int j = 0; j < 2; j++)
                su[nt][j] += __shfl_xor_sync(0xffffffffu, su[nt][j], o);
    if (g == 0) {
#pragma unroll
        for (int nt = 0; nt < 9; nt++)
#pragma unroll
            for (int j = 0; j < 2; j++) {
                int col = nt * 8 + 2 * t + j;
                if (col < CDIM) atomicAdd(&g_sump[col], su[nt][j]);
            }
    }
}

// ---------------- per-class segment sum over feat ----------------
__global__ void __launch_bounds__(128) segsum_kernel(const float* __restrict__ feat)
{
    __shared__ float acc[CDIM * 128];
    const int t   = threadIdx.x;
    const int col = blockIdx.x * 128 + t;
    const int rpb = NROWS / 16;
    const int r0  = blockIdx.y * rpb;

    for (int i = t; i < CDIM * 128; i += 128) acc[i] = 0.f;
    __syncthreads();

    for (int i = r0; i < r0 + rpb; i++) {
        int cls = g_pred[i];
        acc[cls * 128 + t] += feat[(size_t)i * DDIM + col];
    }
    __syncthreads();

    for (int c = 0; c < CDIM; c++)
        atomicAdd(&g_csum[c * DDIM + col], acc[c * 128 + t]);
}

// ---------------- finalize centroids (normalized, transposed tf32) ----------------
__global__ void __launch_bounds__(256) centroid_kernel()
{
    __shared__ float red[256];
    const int c = blockIdx.x;
    const int t = threadIdx.x;
    const int cnt = g_cnt[c];
    const float denom = fmaxf((float)cnt, 1.f);

    float ssq = 0.f;
    for (int d = t; d < DDIM; d += 256) {
        float mv = g_csum[c * DDIM + d] / denom;
        ssq += mv * mv;
    }
    red[t] = ssq;
    __syncthreads();
    for (int o = 128; o > 0; o >>= 1) { if (t < o) red[t] += red[t + o]; __syncthreads(); }
    float nrm   = sqrtf(red[0]);
    float scale = (cnt > 0) ? 1.f / (denom * fmaxf(nrm, 1e-12f)) : 0.f;

    for (int d = t; d < DDIM; d += 256)
        g_centTp[d * CPAD + c] = f2tf32(g_csum[c * DDIM + d] * scale);
}

// ============================================================================
// sim (TF32 TC): sim = feat @ centTp; fused argmax + CE.
// ============================================================================
__global__ void __launch_bounds__(128) sim_tc(const float* __restrict__ feat)
{
    __shared__ unsigned As[64 * 36];
    __shared__ unsigned Bs[32 * 76];

    const int tid  = threadIdx.x;
    const int lane = tid & 31;
    const int w    = tid >> 5;
    const int g    = lane >> 2;
    const int t    = lane & 3;
    const int row0 = blockIdx.x * 64;

    const int ar = tid >> 3;
    const int af = (tid & 7) * 4;

    int soff[18];
#pragma unroll
    for (int p = 0; p < 18; p++) {
        int i = tid + 128 * p;
        soff[p] = i + 4 * (i / CPAD);
    }

    float acc[9][4];
#pragma unroll
    for (int n = 0; n < 9; n++)
#pragma unroll
        for (int c = 0; c < 4; c++) acc[n][c] = 0.f;

    float4 asg[4];
    unsigned bsg[18];
    const int NT = DDIM / 32;           // 64

#pragma unroll
    for (int p = 0; p < 4; p++)
        asg[p] = *reinterpret_cast<const float4*>(&feat[(size_t)(row0 + ar + 16 * p) * DDIM + af]);
#pragma unroll
    for (int p = 0; p < 18; p++)
        bsg[p] = g_centTp[tid + 128 * p];

    for (int kt = 0; kt < NT; kt++) {
#pragma unroll
        for (int p = 0; p < 4; p++) {
            int rb = (ar + 16 * p) * 36 + af;
            As[rb + 0] = f2tf32(asg[p].x); As[rb + 1] = f2tf32(asg[p].y);
            As[rb + 2] = f2tf32(asg[p].z); As[rb + 3] = f2tf32(asg[p].w);
        }
#pragma unroll
        for (int p = 0; p < 18; p++) Bs[soff[p]] = bsg[p];
        __syncthreads();

        if (kt + 1 < NT) {
            int k0n = (kt + 1) * 32;
#pragma unroll
            for (int p = 0; p < 4; p++)
                asg[p] = *reinterpret_cast<const float4*>(&feat[(size_t)(row0 + ar + 16 * p) * DDIM + k0n + af]);
#pragma unroll
            for (int p = 0; p < 18; p++)
                bsg[p] = g_centTp[k0n * CPAD + tid + 128 * p];
        }

#pragma unroll
        for (int ks = 0; ks < 4; ks++) {
            int k0 = ks * 8;
            int row = w * 16;
            unsigned a0 = As[(row + g) * 36 + k0 + t];
            unsigned a1 = As[(row + 8 + g) * 36 + k0 + t];
            unsigned a2 = As[(row + g) * 36 + k0 + t + 4];
            unsigned a3 = As[(row + 8 + g) * 36 + k0 + t + 4];
#pragma unroll
            for (int nt = 0; nt < 9; nt++) {
                unsigned b0 = Bs[(k0 + t) * 76 + nt * 8 + g];
                unsigned b1 = Bs[(k0 + t + 4) * 76 + nt * 8 + g];
                mma_tf32(acc[nt], a0, a1, a2, a3, b0, b1);
            }
        }
        __syncthreads();
    }

    // ---- epilogue: argmax + CE ----
    float ceL = 0.f;
#pragma unroll
    for (int half = 0; half < 2; half++) {
        int row = row0 + w * 16 + g + 8 * half;
        int ci  = 2 * half;

        float bv = -1e30f; int bi = CDIM;
#pragma unroll
        for (int nt = 0; nt < 9; nt++)
#pragma unroll
            for (int j = 0; j < 2; j++) {
                int col = nt * 8 + 2 * t + j;
                if (col < CDIM) {
                    float vv = acc[nt][ci + j];
                    if (vv > bv || (vv == bv && col < bi)) { bv = vv; bi = col; }
                }
            }
#pragma unroll
        for (int o = 1; o <= 2; o <<= 1) {
            float ov = __shfl_xor_sync(0xffffffffu, bv, o);
            int   oi = __shfl_xor_sync(0xffffffffu, bi, o);
            if (ov > bv || (ov == bv && oi < bi)) { bv = ov; bi = oi; }
        }
        if (t == 0)
            ceL += g_lse[row] - g_logits[row * CDIM + bi];
    }
#pragma unroll
    for (int o = 16; o > 0; o >>= 1) ceL += __shfl_xor_sync(0xffffffffu, ceL, o);
    if (lane == 0) atomicAdd(&g_ce, ceL);
}

// ---------------- final scalar ----------------
__global__ void finalize_kernel(float* __restrict__ out)
{
    __shared__ float red[128];
    int t = threadIdx.x;
    float v = 0.f;
    if (t < CDIM) {
        float mp = g_sump[t] * (1.f / NROWS);
        v = mp * logf(mp + 1e-6f);
    }
    red[t] = v;
    __syncthreads();
    for (int o = 64; o > 0; o >>= 1) { if (t < o) red[t] += red[t + o]; __syncthreads(); }
    if (t == 0) {
        float entropy = -g_ent * (1.f / NROWS);
        float ce      =  g_ce  * (1.f / NROWS);
        out[0] = entropy + red[0] + 0.3f * ce;
    }
}

// ---------------- launch ----------------
extern "C" void kernel_launch(void* const* d_in, const int* in_sizes, int n_in,
                              void* d_out, int out_size)
{
    const float* feat = (const float*)d_in[0];
    const float* w1   = (const float*)d_in[1];
    const float* b1   = (const float*)d_in[2];
    const float* w2   = (const float*)d_in[3];
    const float* b2   = (const float*)d_in[4];
    float* out = (float*)d_out;

    zero_kernel<<<(DDIM * CPAD + 255) / 256, 256>>>();
    pad_w2_kernel<<<(HDIM * CPAD + 255) / 256, 256>>>(w2);
    mask_kernel<<<(NROWS * HDIM + 255) / 256, 256>>>();
    gemm1_tc<<<dim3(HDIM / 128, NROWS / 128), 256>>>(feat, w1, b1);
    logits_tc<<<NROWS / 64, 128>>>(b2);
    segsum_kernel<<<dim3(DDIM / 128, 16), 128>>>(feat);
    centroid_kernel<<<CDIM, 256>>>();
    sim_tc<<<NROWS / 64, 128>>>(feat);
    finalize_kernel<<<1, 128>>>(out);
}

// round 6
// speedup vs baseline: 4.0445x; 1.1349x over previous
#include <cuda_runtime.h>
#include <cuda_fp16.h>
#include <math.h>
#include <stdint.h>

#define NROWS 16384
#define DDIM  2048
#define HDIM  512
#define CDIM  65
#define CPAD  72
#define KPAIRS (DDIM / 2)

// ---------------- scratch (device globals; no allocation) ----------------
__device__ float         g_h[NROWS * HDIM];        // post-dropout hidden (fp32)
__device__ float         g_logits[NROWS * CDIM];
__device__ float         g_lse[NROWS];
__device__ int           g_pred[NROWS];
__device__ float         g_sump[CDIM];
__device__ float         g_ent;
__device__ float         g_ce;
__device__ float         g_csum[CDIM * DDIM];
__device__ int           g_cnt[CDIM];
__device__ unsigned      g_w2p[HDIM * CPAD];       // tf32 bits, padded
__device__ unsigned      g_centTp[DDIM * CPAD];    // tf32 bits, padded, [D][CPAD]
__device__ unsigned      g_w1Th[HDIM * KPAIRS];    // half2 pairs, [n][kpair]

// ---------------- helpers ----------------
__device__ __forceinline__ unsigned f2tf32(float x)
{
    unsigned u;
    asm("cvt.rna.tf32.f32 %0, %1;" : "=r"(u) : "f"(x));
    return u;
}

__device__ __forceinline__ unsigned pack_h2(float a, float b)
{
    __half2 h = __floats2half2_rn(a, b);
    return *reinterpret_cast<unsigned*>(&h);
}

__device__ __forceinline__ void mma_tf32(float c[4],
                                         unsigned a0, unsigned a1, unsigned a2, unsigned a3,
                                         unsigned b0, unsigned b1)
{
    asm volatile(
        "mma.sync.aligned.m16n8k8.row.col.f32.tf32.tf32.f32 "
        "{%0,%1,%2,%3}, {%4,%5,%6,%7}, {%8,%9}, {%0,%1,%2,%3};"
        : "+f"(c[0]), "+f"(c[1]), "+f"(c[2]), "+f"(c[3])
        : "r"(a0), "r"(a1), "r"(a2), "r"(a3), "r"(b0), "r"(b1));
}

__device__ __forceinline__ void mma_f16(float c[4],
                                        unsigned a0, unsigned a1, unsigned a2, unsigned a3,
                                        unsigned b0, unsigned b1)
{
    asm volatile(
        "mma.sync.aligned.m16n8k16.row.col.f32.f16.f16.f32 "
        "{%0,%1,%2,%3}, {%4,%5,%6,%7}, {%8,%9}, {%0,%1,%2,%3};"
        : "+f"(c[0]), "+f"(c[1]), "+f"(c[2]), "+f"(c[3])
        : "r"(a0), "r"(a1), "r"(a2), "r"(a3), "r"(b0), "r"(b1));
}

// ---------------- threefry2x32 (JAX partitionable, key = (0, 42)) ----------------
__device__ __forceinline__ void threefry2x32_42(unsigned c0, unsigned c1,
                                                unsigned& o0, unsigned& o1)
{
    const unsigned ks0 = 0u;
    const unsigned ks1 = 42u;
    const unsigned ks2 = 0x1BD11BDAu ^ 0u ^ 42u;
    unsigned x0 = c0 + ks0;
    unsigned x1 = c1 + ks1;
#define TF_ROUND(r) { x0 += x1; x1 = (x1 << (r)) | (x1 >> (32 - (r))); x1 ^= x0; }
    TF_ROUND(13) TF_ROUND(15) TF_ROUND(26) TF_ROUND(6)
    x0 += ks1; x1 += ks2 + 1u;
    TF_ROUND(17) TF_ROUND(29) TF_ROUND(16) TF_ROUND(24)
    x0 += ks2; x1 += ks0 + 2u;
    TF_ROUND(13) TF_ROUND(15) TF_ROUND(26) TF_ROUND(6)
    x0 += ks0; x1 += ks1 + 3u;
    TF_ROUND(17) TF_ROUND(29) TF_ROUND(16) TF_ROUND(24)
    x0 += ks1; x1 += ks2 + 4u;
    TF_ROUND(13) TF_ROUND(15) TF_ROUND(26) TF_ROUND(6)
    x0 += ks2; x1 += ks0 + 5u;
#undef TF_ROUND
    o0 = x0; o1 = x1;
}

// keep <=> top bit of truncated 64-bit output (= x1) is 0
__device__ __forceinline__ bool keep_bit(unsigned idx)
{
    unsigned a, b;
    threefry2x32_42(0u, idx, a, b);
    return (b >> 31) == 0u;
}

__global__ void zero_kernel()
{
    int i = blockIdx.x * blockDim.x + threadIdx.x;
    if (i < DDIM * CPAD) g_centTp[i] = 0u;
    if (i < CDIM * DDIM) g_csum[i] = 0.f;
    if (i < CDIM) { g_sump[i] = 0.f; g_cnt[i] = 0; }
    if (i == 0) { g_ent = 0.f; g_ce = 0.f; }
}

__global__ void pad_w2_kernel(const float* __restrict__ w2)
{
    int i = blockIdx.x * blockDim.x + threadIdx.x;
    if (i >= HDIM * CPAD) return;
    int row = i / CPAD, col = i - row * CPAD;
    g_w2p[i] = (col < CDIM) ? f2tf32(w2[row * CDIM + col]) : 0u;
}

// w1 [K=2048][N=512] -> g_w1Th [N][KPAIRS] half2 pairs (tiled transpose)
__global__ void __launch_bounds__(256) w1t_kernel(const float* __restrict__ w1)
{
    __shared__ float t[32][33];
    const int k0 = blockIdx.x * 32, n0 = blockIdx.y * 32;
    const int x = threadIdx.x, y = threadIdx.y;
#pragma unroll
    for (int i = y; i < 32; i += 8) t[i][x] = w1[(size_t)(k0 + i) * HDIM + n0 + x];
    __syncthreads();
#pragma unroll
    for (int i = y; i < 16; i += 8)
        g_w1Th[(size_t)(n0 + x) * KPAIRS + k0 / 2 + i] = pack_h2(t[2 * i][x], t[2 * i + 1][x]);
}

// ============================================================================
// GEMM1 (fp16 mma m16n8k16): g_h = dropout(relu(feat @ w1 + b1))
// CTA 128x128, BK=32 (16 pairs), 256 threads, 8 warps of 64x32.
// A/B in smem as b32 pairs, stride 20 (conflict-free fragment reads).
// Double-buffered; threefry dropout fused into epilogue.
// ============================================================================
#define SA 20

__global__ void __launch_bounds__(256) gemm1_fp16(const float* __restrict__ A,
                                                  const float* __restrict__ bias)
{
    __shared__ unsigned As[2][128 * SA];
    __shared__ unsigned Bs[2][128 * SA];
    __shared__ float sb[128];

    const int tid  = threadIdx.x;
    const int lane = tid & 31;
    const int w    = tid >> 5;
    const int g    = lane >> 2;
    const int t    = lane & 3;
    const int wm   = w & 1;             // 2 row tiles of 64
    const int wn   = w >> 1;            // 4 col tiles of 32
    const int brow = blockIdx.y * 128;
    const int bcol = blockIdx.x * 128;

    if (tid < 128) sb[tid] = bias[bcol + tid];

    const int arow = tid >> 3;          // 0..31
    const int af4  = tid & 7;           // float4 index within 32-k
    const int bcl  = tid & 127;         // B col
    const int bq   = (tid >> 7) * 2;    // uint4 pair offset (0 or 2)

    float acc[4][4][4];
#pragma unroll
    for (int i = 0; i < 4; i++)
#pragma unroll
        for (int j = 0; j < 4; j++)
#pragma unroll
            for (int c = 0; c < 4; c++) acc[i][j][c] = 0.f;

    float4 av[4];
    uint4  bv[2];
    const int NT = DDIM / 32;           // 64

#pragma unroll
    for (int p = 0; p < 4; p++)
        av[p] = *reinterpret_cast<const float4*>(&A[(size_t)(brow + arow + 32 * p) * DDIM + af4 * 4]);
#pragma unroll
    for (int q = 0; q < 2; q++)
        bv[q] = *reinterpret_cast<const uint4*>(&g_w1Th[(size_t)(bcol + bcl) * KPAIRS + (bq + q) * 4]);

    for (int kt = 0; kt < NT; kt++) {
        const int buf = kt & 1;
#pragma unroll
        for (int p = 0; p < 4; p++) {
            unsigned* d = &As[buf][(arow + 32 * p) * SA + af4 * 2];
            d[0] = pack_h2(av[p].x, av[p].y);
            d[1] = pack_h2(av[p].z, av[p].w);
        }
#pragma unroll
        for (int q = 0; q < 2; q++)
            *reinterpret_cast<uint4*>(&Bs[buf][bcl * SA + (bq + q) * 4]) = bv[q];

        if (kt + 1 < NT) {
            int k0n = (kt + 1) * 32;
#pragma unroll
            for (int p = 0; p < 4; p++)
                av[p] = *reinterpret_cast<const float4*>(
                    &A[(size_t)(brow + arow + 32 * p) * DDIM + k0n + af4 * 4]);
#pragma unroll
            for (int q = 0; q < 2; q++)
                bv[q] = *reinterpret_cast<const uint4*>(
                    &g_w1Th[(size_t)(bcol + bcl) * KPAIRS + (kt + 1) * 16 + (bq + q) * 4]);
        }
        __syncthreads();

#pragma unroll
        for (int ks = 0; ks < 2; ks++) {
            const int kp = ks * 8;
            unsigned afr[4][4];
#pragma unroll
            for (int mt = 0; mt < 4; mt++) {
                int row = wm * 64 + mt * 16;
                afr[mt][0] = As[buf][(row + g) * SA + kp + t];
                afr[mt][1] = As[buf][(row + 8 + g) * SA + kp + t];
                afr[mt][2] = As[buf][(row + g) * SA + kp + 4 + t];
                afr[mt][3] = As[buf][(row + 8 + g) * SA + kp + 4 + t];
            }
            unsigned bfr[4][2];
#pragma unroll
            for (int nt = 0; nt < 4; nt++) {
                int col = wn * 32 + nt * 8;
                bfr[nt][0] = Bs[buf][(col + g) * SA + kp + t];
                bfr[nt][1] = Bs[buf][(col + g) * SA + kp + 4 + t];
            }
#pragma unroll
            for (int mt = 0; mt < 4; mt++)
#pragma unroll
                for (int nt = 0; nt < 4; nt++)
                    mma_f16(acc[mt][nt], afr[mt][0], afr[mt][1], afr[mt][2], afr[mt][3],
                            bfr[nt][0], bfr[nt][1]);
        }
    }

    // epilogue: bias + relu + threefry dropout -> g_h (fp32)
#pragma unroll
    for (int mt = 0; mt < 4; mt++) {
#pragma unroll
        for (int h = 0; h < 2; h++) {
            int row = brow + wm * 64 + mt * 16 + g + 8 * h;
#pragma unroll
            for (int nt = 0; nt < 4; nt++) {
                int colL = wn * 32 + nt * 8 + 2 * t;
                unsigned i0 = (unsigned)(row * HDIM + bcol + colL);
                float v0 = fmaxf(acc[mt][nt][2 * h + 0] + sb[colL], 0.f);
                float v1 = fmaxf(acc[mt][nt][2 * h + 1] + sb[colL + 1], 0.f);
                float2 o;
                o.x = keep_bit(i0)     ? (v0 + v0) : 0.f;
                o.y = keep_bit(i0 + 1) ? (v1 + v1) : 0.f;
                *reinterpret_cast<float2*>(&g_h[i0]) = o;
            }
        }
    }
}

// ============================================================================
// logits (TF32 mma.sync): logits = g_h @ w2p + b2; fused stats/argmax/counts.
// 128 rows x 72 cols per block, 256 threads, 8 warps of 16 rows; BK=32.
// ============================================================================
__global__ void __launch_bounds__(256) logits_tc(const float* __restrict__ b2)
{
    __shared__ unsigned As[128 * 36];
    __shared__ unsigned Bs[32 * 76];

    const int tid  = threadIdx.x;
    const int lane = tid & 31;
    const int w    = tid >> 5;
    const int g    = lane >> 2;
    const int t    = lane & 3;
    const int row0 = blockIdx.x * 128;

    const int ar = tid >> 3;            // 0..31
    const int af = (tid & 7) * 4;

    int soff[9];
#pragma unroll
    for (int p = 0; p < 9; p++) {
        int i = tid + 256 * p;
        soff[p] = i + 4 * (i / CPAD);
    }

    float acc[9][4];
#pragma unroll
    for (int n = 0; n < 9; n++)
#pragma unroll
        for (int c = 0; c < 4; c++) acc[n][c] = 0.f;

    float4 asg[4];
    unsigned bsg[9];
    const int NT = HDIM / 32;

#pragma unroll
    for (int p = 0; p < 4; p++)
        asg[p] = *reinterpret_cast<const float4*>(&g_h[(size_t)(row0 + ar + 32 * p) * HDIM + af]);
#pragma unroll
    for (int p = 0; p < 9; p++)
        bsg[p] = g_w2p[tid + 256 * p];

    for (int kt = 0; kt < NT; kt++) {
#pragma unroll
        for (int p = 0; p < 4; p++) {
            int rb = (ar + 32 * p) * 36 + af;
            As[rb + 0] = f2tf32(asg[p].x); As[rb + 1] = f2tf32(asg[p].y);
            As[rb + 2] = f2tf32(asg[p].z); As[rb + 3] = f2tf32(asg[p].w);
        }
#pragma unroll
        for (int p = 0; p < 9; p++) Bs[soff[p]] = bsg[p];
        __syncthreads();

        if (kt + 1 < NT) {
            int k0n = (kt + 1) * 32;
#pragma unroll
            for (int p = 0; p < 4; p++)
                asg[p] = *reinterpret_cast<const float4*>(&g_h[(size_t)(row0 + ar + 32 * p) * HDIM + k0n + af]);
#pragma unroll
            for (int p = 0; p < 9; p++)
                bsg[p] = g_w2p[k0n * CPAD + tid + 256 * p];
        }

#pragma unroll
        for (int ks = 0; ks < 4; ks++) {
            int k0 = ks * 8;
            int row = w * 16;
            unsigned a0 = As[(row + g) * 36 + k0 + t];
            unsigned a1 = As[(row + 8 + g) * 36 + k0 + t];
            unsigned a2 = As[(row + g) * 36 + k0 + t + 4];
            unsigned a3 = As[(row + 8 + g) * 36 + k0 + t + 4];
#pragma unroll
            for (int nt = 0; nt < 9; nt++) {
                unsigned b0 = Bs[(k0 + t) * 76 + nt * 8 + g];
                unsigned b1 = Bs[(k0 + t + 4) * 76 + nt * 8 + g];
                mma_tf32(acc[nt], a0, a1, a2, a3, b0, b1);
            }
        }
        __syncthreads();
    }

    float su[9][2];
#pragma unroll
    for (int n = 0; n < 9; n++) { su[n][0] = 0.f; su[n][1] = 0.f; }
    float entL = 0.f;

#pragma unroll
    for (int half = 0; half < 2; half++) {
        int row = row0 + w * 16 + g + 8 * half;
        int ci  = 2 * half;

        float v[9][2];
        float m = -1e30f;
#pragma unroll
        for (int nt = 0; nt < 9; nt++)
#pragma unroll
            for (int j = 0; j < 2; j++) {
                int col = nt * 8 + 2 * t + j;
                v[nt][j] = (col < CDIM) ? acc[nt][ci + j] + b2[col] : -1e30f;
                m = fmaxf(m, v[nt][j]);
            }
        m = fmaxf(m, __shfl_xor_sync(0xffffffffu, m, 1));
        m = fmaxf(m, __shfl_xor_sync(0xffffffffu, m, 2));

        float s = 0.f;
#pragma unroll
        for (int nt = 0; nt < 9; nt++)
#pragma unroll
            for (int j = 0; j < 2; j++) {
                int col = nt * 8 + 2 * t + j;
                if (col < CDIM) s += expf(v[nt][j] - m);
            }
        s += __shfl_xor_sync(0xffffffffu, s, 1);
        s += __shfl_xor_sync(0xffffffffu, s, 2);
        float lse = m + logf(s);

        float bv = -1e30f; int bi = CDIM;
#pragma unroll
        for (int nt = 0; nt < 9; nt++)
#pragma unroll
            for (int j = 0; j < 2; j++) {
                int col = nt * 8 + 2 * t + j;
                if (col < CDIM) {
                    float p = expf(v[nt][j] - lse);
                    entL += p * logf(p + 1e-6f);
                    su[nt][j] += p;
                    g_logits[row * CDIM + col] = v[nt][j];
                    if (v[nt][j] > bv || (v[nt][j] == bv && col < bi)) { bv = v[nt][j]; bi = col; }
                }
            }
#pragma unroll
        for (int o = 1; o <= 2; o <<= 1) {
            float ov = __shfl_xor_sync(0xffffffffu, bv, o);
            int   oi = __shfl_xor_sync(0xffffffffu, bi, o);
            if (ov > bv || (ov == bv && oi < bi)) { bv = ov; bi = oi; }
        }
        if (t == 0) {
            g_lse[row]  = lse;
            g_pred[row] = bi;
            atomicAdd(&g_cnt[bi], 1);
        }
    }

#pragma unroll
    for (int o = 16; o > 0; o >>= 1) entL += __shfl_xor_sync(0xffffffffu, entL, o);
    if (lane == 0) atomicAdd(&g_ent, entL);

#pragma unroll
    for (int o = 4; o <= 16; o <<= 1)
#pragma unroll
        for (int nt = 0; nt < 9; nt++)
#pragma unroll
            for (int j = 0; j < 2; j++)
                su[nt][j] += __shfl_xor_sync(0xffffffffu, su[nt][j], o);
    if (g == 0) {
#pragma unroll
        for (int nt = 0; nt < 9; nt++)
#pragma unroll
            for (int j = 0; j < 2; j++) {
                int col = nt * 8 + 2 * t + j;
                if (col < CDIM) atomicAdd(&g_sump[col], su[nt][j]);
            }
    }
}

// ---------------- per-class segment sum over feat ----------------
__global__ void __launch_bounds__(128) segsum_kernel(const float* __restrict__ feat)
{
    __shared__ float acc[CDIM * 128];
    const int t   = threadIdx.x;
    const int col = blockIdx.x * 128 + t;
    const int rpb = NROWS / 32;
    const int r0  = blockIdx.y * rpb;

    for (int i = t; i < CDIM * 128; i += 128) acc[i] = 0.f;
    __syncthreads();

    for (int i = r0; i < r0 + rpb; i++) {
        int cls = g_pred[i];
        acc[cls * 128 + t] += feat[(size_t)i * DDIM + col];
    }
    __syncthreads();

    for (int c = 0; c < CDIM; c++)
        atomicAdd(&g_csum[c * DDIM + col], acc[c * 128 + t]);
}

// ---------------- finalize centroids (normalized, transposed tf32) ----------------
__global__ void __launch_bounds__(256) centroid_kernel()
{
    __shared__ float red[256];
    const int c = blockIdx.x;
    const int t = threadIdx.x;
    const int cnt = g_cnt[c];
    const float denom = fmaxf((float)cnt, 1.f);

    float ssq = 0.f;
    for (int d = t; d < DDIM; d += 256) {
        float mv = g_csum[c * DDIM + d] / denom;
        ssq += mv * mv;
    }
    red[t] = ssq;
    __syncthreads();
    for (int o = 128; o > 0; o >>= 1) { if (t < o) red[t] += red[t + o]; __syncthreads(); }
    float nrm   = sqrtf(red[0]);
    float scale = (cnt > 0) ? 1.f / (denom * fmaxf(nrm, 1e-12f)) : 0.f;

    for (int d = t; d < DDIM; d += 256)
        g_centTp[d * CPAD + c] = f2tf32(g_csum[c * DDIM + d] * scale);
}

// ============================================================================
// sim (TF32 mma.sync): sim = feat @ centTp; fused argmax + CE.
// 128 rows/block, 256 threads.
// ============================================================================
__global__ void __launch_bounds__(256) sim_tc(const float* __restrict__ feat)
{
    __shared__ unsigned As[128 * 36];
    __shared__ unsigned Bs[32 * 76];

    const int tid  = threadIdx.x;
    const int lane = tid & 31;
    const int w    = tid >> 5;
    const int g    = lane >> 2;
    const int t    = lane & 3;
    const int row0 = blockIdx.x * 128;

    const int ar = tid >> 3;
    const int af = (tid & 7) * 4;

    int soff[9];
#pragma unroll
    for (int p = 0; p < 9; p++) {
        int i = tid + 256 * p;
        soff[p] = i + 4 * (i / CPAD);
    }

    float acc[9][4];
#pragma unroll
    for (int n = 0; n < 9; n++)
#pragma unroll
        for (int c = 0; c < 4; c++) acc[n][c] = 0.f;

    float4 asg[4];
    unsigned bsg[9];
    const int NT = DDIM / 32;

#pragma unroll
    for (int p = 0; p < 4; p++)
        asg[p] = *reinterpret_cast<const float4*>(&feat[(size_t)(row0 + ar + 32 * p) * DDIM + af]);
#pragma unroll
    for (int p = 0; p < 9; p++)
        bsg[p] = g_centTp[tid + 256 * p];

    for (int kt = 0; kt < NT; kt++) {
#pragma unroll
        for (int p = 0; p < 4; p++) {
            int rb = (ar + 32 * p) * 36 + af;
            As[rb + 0] = f2tf32(asg[p].x); As[rb + 1] = f2tf32(asg[p].y);
            As[rb + 2] = f2tf32(asg[p].z); As[rb + 3] = f2tf32(asg[p].w);
        }
#pragma unroll
        for (int p = 0; p < 9; p++) Bs[soff[p]] = bsg[p];
        __syncthreads();

        if (kt + 1 < NT) {
            int k0n = (kt + 1) * 32;
#pragma unroll
            for (int p = 0; p < 4; p++)
                asg[p] = *reinterpret_cast<const float4*>(&feat[(size_t)(row0 + ar + 32 * p) * DDIM + k0n + af]);
#pragma unroll
            for (int p = 0; p < 9; p++)
                bsg[p] = g_centTp[k0n * CPAD + tid + 256 * p];
        }

#pragma unroll
        for (int ks = 0; ks < 4; ks++) {
            int k0 = ks * 8;
            int row = w * 16;
            unsigned a0 = As[(row + g) * 36 + k0 + t];
            unsigned a1 = As[(row + 8 + g) * 36 + k0 + t];
            unsigned a2 = As[(row + g) * 36 + k0 + t + 4];
            unsigned a3 = As[(row + 8 + g) * 36 + k0 + t + 4];
#pragma unroll
            for (int nt = 0; nt < 9; nt++) {
                unsigned b0 = Bs[(k0 + t) * 76 + nt * 8 + g];
                unsigned b1 = Bs[(k0 + t + 4) * 76 + nt * 8 + g];
                mma_tf32(acc[nt], a0, a1, a2, a3, b0, b1);
            }
        }
        __syncthreads();
    }

    float ceL = 0.f;
#pragma unroll
    for (int half = 0; half < 2; half++) {
        int row = row0 + w * 16 + g + 8 * half;
        int ci  = 2 * half;

        float bv = -1e30f; int bi = CDIM;
#pragma unroll
        for (int nt = 0; nt < 9; nt++)
#pragma unroll
            for (int j = 0; j < 2; j++) {
                int col = nt * 8 + 2 * t + j;
                if (col < CDIM) {
                    float vv = acc[nt][ci + j];
                    if (vv > bv || (vv == bv && col < bi)) { bv = vv; bi = col; }
                }
            }
#pragma unroll
        for (int o = 1; o <= 2; o <<= 1) {
            float ov = __shfl_xor_sync(0xffffffffu, bv, o);
            int   oi = __shfl_xor_sync(0xffffffffu, bi, o);
            if (ov > bv || (ov == bv && oi < bi)) { bv = ov; bi = oi; }
        }
        if (t == 0)
            ceL += g_lse[row] - g_logits[row * CDIM + bi];
    }
#pragma unroll
    for (int o = 16; o > 0; o >>= 1) ceL += __shfl_xor_sync(0xffffffffu, ceL, o);
    if (lane == 0) atomicAdd(&g_ce, ceL);
}

// ---------------- final scalar ----------------
__global__ void finalize_kernel(float* __restrict__ out)
{
    __shared__ float red[128];
    int t = threadIdx.x;
    float v = 0.f;
    if (t < CDIM) {
        float mp = g_sump[t] * (1.f / NROWS);
        v = mp * logf(mp + 1e-6f);
    }
    red[t] = v;
    __syncthreads();
    for (int o = 64; o > 0; o >>= 1) { if (t < o) red[t] += red[t + o]; __syncthreads(); }
    if (t == 0) {
        float entropy = -g_ent * (1.f / NROWS);
        float ce      =  g_ce  * (1.f / NROWS);
        out[0] = entropy + red[0] + 0.3f * ce;
    }
}

// ---------------- launch ----------------
extern "C" void kernel_launch(void* const* d_in, const int* in_sizes, int n_in,
                              void* d_out, int out_size)
{
    const float* feat = (const float*)d_in[0];
    const float* w1   = (const float*)d_in[1];
    const float* b1   = (const float*)d_in[2];
    const float* w2   = (const float*)d_in[3];
    const float* b2   = (const float*)d_in[4];
    float* out = (float*)d_out;

    zero_kernel<<<(DDIM * CPAD + 255) / 256, 256>>>();
    pad_w2_kernel<<<(HDIM * CPAD + 255) / 256, 256>>>(w2);
    w1t_kernel<<<dim3(DDIM / 32, HDIM / 32), dim3(32, 8)>>>(w1);
    gemm1_fp16<<<dim3(HDIM / 128, NROWS / 128), 256>>>(feat, b1);
    logits_tc<<<NROWS / 128, 256>>>(b2);
    segsum_kernel<<<dim3(DDIM / 128, 32), 128>>>(feat);
    centroid_kernel<<<CDIM, 256>>>();
    sim_tc<<<NROWS / 128, 256>>>(feat);
    finalize_kernel<<<1, 128>>>(out);
}

// round 7
// speedup vs baseline: 4.7490x; 1.1742x over previous
#include <cuda_runtime.h>
#include <cuda_fp16.h>
#include <math.h>
#include <stdint.h>

#define NROWS 16384
#define DDIM  2048
#define HDIM  512
#define CDIM  65
#define CPAD  72
#define KPAIRS (DDIM / 2)

// ---------------- scratch (device globals; no allocation) ----------------
__device__ float         g_h[NROWS * HDIM];        // post-dropout hidden (fp32)
__device__ __half        g_feat16[NROWS * DDIM];   // feat converted to fp16
__device__ float         g_logits[NROWS * CDIM];
__device__ float         g_lse[NROWS];
__device__ int           g_pred[NROWS];
__device__ float         g_sump[CDIM];
__device__ float         g_ent;
__device__ float         g_ce;
__device__ float         g_csum[CDIM * DDIM];
__device__ int           g_cnt[CDIM];
__device__ unsigned      g_w2p[HDIM * CPAD];       // tf32 bits, padded
__device__ unsigned      g_centTp[DDIM * CPAD];    // tf32 bits, padded, [D][CPAD]
__device__ unsigned      g_w1Th[HDIM * KPAIRS];    // half2 pairs, [n][k] row-major

// ---------------- helpers ----------------
__device__ __forceinline__ unsigned f2tf32(float x)
{
    unsigned u;
    asm("cvt.rna.tf32.f32 %0, %1;" : "=r"(u) : "f"(x));
    return u;
}

__device__ __forceinline__ unsigned pack_h2(float a, float b)
{
    __half2 h = __floats2half2_rn(a, b);
    return *reinterpret_cast<unsigned*>(&h);
}

__device__ __forceinline__ unsigned smem_u32(const void* p)
{
    unsigned a;
    asm("{ .reg .u64 t; cvta.to.shared.u64 t, %1; cvt.u32.u64 %0, t; }" : "=r"(a) : "l"(p));
    return a;
}

__device__ __forceinline__ void mma_tf32(float c[4],
                                         unsigned a0, unsigned a1, unsigned a2, unsigned a3,
                                         unsigned b0, unsigned b1)
{
    asm volatile(
        "mma.sync.aligned.m16n8k8.row.col.f32.tf32.tf32.f32 "
        "{%0,%1,%2,%3}, {%4,%5,%6,%7}, {%8,%9}, {%0,%1,%2,%3};"
        : "+f"(c[0]), "+f"(c[1]), "+f"(c[2]), "+f"(c[3])
        : "r"(a0), "r"(a1), "r"(a2), "r"(a3), "r"(b0), "r"(b1));
}

__device__ __forceinline__ void mma_f16(float c[4],
                                        unsigned a0, unsigned a1, unsigned a2, unsigned a3,
                                        unsigned b0, unsigned b1)
{
    asm volatile(
        "mma.sync.aligned.m16n8k16.row.col.f32.f16.f16.f32 "
        "{%0,%1,%2,%3}, {%4,%5,%6,%7}, {%8,%9}, {%0,%1,%2,%3};"
        : "+f"(c[0]), "+f"(c[1]), "+f"(c[2]), "+f"(c[3])
        : "r"(a0), "r"(a1), "r"(a2), "r"(a3), "r"(b0), "r"(b1));
}

__device__ __forceinline__ void ldsm_x4(unsigned& r0, unsigned& r1, unsigned& r2, unsigned& r3,
                                        unsigned saddr)
{
    asm volatile("ldmatrix.sync.aligned.m8n8.x4.shared.b16 {%0,%1,%2,%3}, [%4];"
                 : "=r"(r0), "=r"(r1), "=r"(r2), "=r"(r3) : "r"(saddr));
}

#define CP_ASYNC16(dst, src) \
    asm volatile("cp.async.cg.shared.global [%0], [%1], 16;" :: "r"(dst), "l"(src))
#define CP_COMMIT() asm volatile("cp.async.commit_group;")
#define CP_WAIT(n)  asm volatile("cp.async.wait_group %0;" :: "n"(n))

// ---------------- threefry2x32 (JAX partitionable, key = (0, 42)) ----------------
__device__ __forceinline__ void threefry2x32_42(unsigned c0, unsigned c1,
                                                unsigned& o0, unsigned& o1)
{
    const unsigned ks0 = 0u;
    const unsigned ks1 = 42u;
    const unsigned ks2 = 0x1BD11BDAu ^ 0u ^ 42u;
    unsigned x0 = c0 + ks0;
    unsigned x1 = c1 + ks1;
#define TF_ROUND(r) { x0 += x1; x1 = (x1 << (r)) | (x1 >> (32 - (r))); x1 ^= x0; }
    TF_ROUND(13) TF_ROUND(15) TF_ROUND(26) TF_ROUND(6)
    x0 += ks1; x1 += ks2 + 1u;
    TF_ROUND(17) TF_ROUND(29) TF_ROUND(16) TF_ROUND(24)
    x0 += ks2; x1 += ks0 + 2u;
    TF_ROUND(13) TF_ROUND(15) TF_ROUND(26) TF_ROUND(6)
    x0 += ks0; x1 += ks1 + 3u;
    TF_ROUND(17) TF_ROUND(29) TF_ROUND(16) TF_ROUND(24)
    x0 += ks1; x1 += ks2 + 4u;
    TF_ROUND(13) TF_ROUND(15) TF_ROUND(26) TF_ROUND(6)
    x0 += ks2; x1 += ks0 + 5u;
#undef TF_ROUND
    o0 = x0; o1 = x1;
}

__device__ __forceinline__ bool keep_bit(unsigned idx)
{
    unsigned a, b;
    threefry2x32_42(0u, idx, a, b);
    return (b >> 31) == 0u;
}

__global__ void zero_kernel()
{
    int i = blockIdx.x * blockDim.x + threadIdx.x;
    if (i < DDIM * CPAD) g_centTp[i] = 0u;
    if (i < CDIM * DDIM) g_csum[i] = 0.f;
    if (i < CDIM) { g_sump[i] = 0.f; g_cnt[i] = 0; }
    if (i == 0) { g_ent = 0.f; g_ce = 0.f; }
}

__global__ void pad_w2_kernel(const float* __restrict__ w2)
{
    int i = blockIdx.x * blockDim.x + threadIdx.x;
    if (i >= HDIM * CPAD) return;
    int row = i / CPAD, col = i - row * CPAD;
    g_w2p[i] = (col < CDIM) ? f2tf32(w2[row * CDIM + col]) : 0u;
}

// feat fp32 -> fp16, 8 elements per thread
__global__ void __launch_bounds__(256) feat16_kernel(const float* __restrict__ feat)
{
    size_t i = ((size_t)blockIdx.x * 256 + threadIdx.x) * 8;
    float4 v0 = *reinterpret_cast<const float4*>(feat + i);
    float4 v1 = *reinterpret_cast<const float4*>(feat + i + 4);
    uint4 o;
    o.x = pack_h2(v0.x, v0.y);
    o.y = pack_h2(v0.z, v0.w);
    o.z = pack_h2(v1.x, v1.y);
    o.w = pack_h2(v1.z, v1.w);
    *reinterpret_cast<uint4*>(&g_feat16[i]) = o;
}

// w1 [K=2048][N=512] -> g_w1Th [N][K] half pairs (tiled transpose)
__global__ void __launch_bounds__(256) w1t_kernel(const float* __restrict__ w1)
{
    __shared__ float t[32][33];
    const int k0 = blockIdx.x * 32, n0 = blockIdx.y * 32;
    const int x = threadIdx.x, y = threadIdx.y;
#pragma unroll
    for (int i = y; i < 32; i += 8) t[i][x] = w1[(size_t)(k0 + i) * HDIM + n0 + x];
    __syncthreads();
#pragma unroll
    for (int i = y; i < 16; i += 8)
        g_w1Th[(size_t)(n0 + x) * KPAIRS + k0 / 2 + i] = pack_h2(t[2 * i][x], t[2 * i + 1][x]);
}

// ============================================================================
// GEMM1 (fp16, cp.async + ldmatrix): g_h = dropout(relu(feat @ w1 + b1))
// CTA 128x128, BK=64, 256 threads, 8 warps of 64x32, 2-stage pipeline.
// Smem rows = 64 halves = 128B, 16B-chunk XOR swizzle: phys_c = c ^ (r & 7).
// ============================================================================
#define G1_SMEM (2 * 32768)

__global__ void __launch_bounds__(256) gemm1_fp16(const float* __restrict__ bias)
{
    extern __shared__ __align__(1024) char dsm[];
    __shared__ float sb[128];

    const unsigned sbase = smem_u32(dsm);
    const int tid  = threadIdx.x;
    const int lane = tid & 31;
    const int w    = tid >> 5;
    const int g    = lane >> 2;
    const int t    = lane & 3;
    const int wm   = w & 1;
    const int wn   = w >> 1;
    const int brow = blockIdx.y * 128;
    const int bcol = blockIdx.x * 128;

    if (tid < 128) sb[tid] = bias[bcol + tid];

    const int NT = DDIM / 64;           // 32

    // copy chunk assignment: q = tid + 256*i ; row = q>>3, chunk = q&7
    const int cr = tid >> 3;            // base row (stride 32 rows per i)
    const int cc = tid & 7;

    auto issue_copy = [&](int kt) {
        const unsigned aoff = (kt & 1) * 32768u;
        const unsigned boff = aoff + 16384u;
        const __half* Ag = &g_feat16[(size_t)brow * DDIM + kt * 64];
        const unsigned* Bg = &g_w1Th[(size_t)bcol * KPAIRS + kt * 32];
#pragma unroll
        for (int i = 0; i < 4; i++) {
            int r = cr + 32 * i;
            unsigned dsw = (unsigned)((cc ^ (r & 7)) << 4);
            CP_ASYNC16(sbase + aoff + r * 128 + dsw, Ag + (size_t)r * DDIM + cc * 8);
            CP_ASYNC16(sbase + boff + r * 128 + dsw, Bg + (size_t)r * KPAIRS + cc * 4);
        }
        CP_COMMIT();
    };

    float acc[4][4][4];
#pragma unroll
    for (int i = 0; i < 4; i++)
#pragma unroll
        for (int j = 0; j < 4; j++)
#pragma unroll
            for (int c = 0; c < 4; c++) acc[i][j][c] = 0.f;

    issue_copy(0);

    for (int kt = 0; kt < NT; kt++) {
        if (kt + 1 < NT) { issue_copy(kt + 1); CP_WAIT(1); }
        else             { CP_WAIT(0); }
        __syncthreads();

        const unsigned aoff = (kt & 1) * 32768u;
        const unsigned boff = aoff + 16384u;

        // B lane address row: n = wn*32 + lane
        const int bn = wn * 32 + lane;
        const unsigned bline = sbase + boff + bn * 128;
        // A lane address row: row = wm*64 + mt*16 + (lane&15)
        const int arl = (lane & 15);
        const int ach = (lane >> 4);    // 0/1 -> k chunk offset

#pragma unroll
        for (int ks = 0; ks < 4; ks++) {
            unsigned b0[4], b1[4];
            {
                int c0 = (2 * ks) ^ (bn & 7);
                int c1 = (2 * ks + 1) ^ (bn & 7);
                ldsm_x4(b0[0], b0[1], b0[2], b0[3], bline + (c0 << 4));
                ldsm_x4(b1[0], b1[1], b1[2], b1[3], bline + (c1 << 4));
            }
#pragma unroll
            for (int mt = 0; mt < 4; mt++) {
                int row = wm * 64 + mt * 16 + arl;
                int ch  = (2 * ks + ach) ^ (row & 7);
                unsigned a0, a1, a2, a3;
                ldsm_x4(a0, a1, a2, a3, sbase + aoff + row * 128 + (ch << 4));
#pragma unroll
                for (int nt = 0; nt < 4; nt++)
                    mma_f16(acc[mt][nt], a0, a1, a2, a3, b0[nt], b1[nt]);
            }
        }
        __syncthreads();
    }

    // epilogue: bias + relu + threefry dropout -> g_h (fp32)
#pragma unroll
    for (int mt = 0; mt < 4; mt++) {
#pragma unroll
        for (int h = 0; h < 2; h++) {
            int row = brow + wm * 64 + mt * 16 + g + 8 * h;
#pragma unroll
            for (int nt = 0; nt < 4; nt++) {
                int colL = wn * 32 + nt * 8 + 2 * t;
                unsigned i0 = (unsigned)(row * HDIM + bcol + colL);
                float v0 = fmaxf(acc[mt][nt][2 * h + 0] + sb[colL], 0.f);
                float v1 = fmaxf(acc[mt][nt][2 * h + 1] + sb[colL + 1], 0.f);
                float2 o;
                o.x = keep_bit(i0)     ? (v0 + v0) : 0.f;
                o.y = keep_bit(i0 + 1) ? (v1 + v1) : 0.f;
                *reinterpret_cast<float2*>(&g_h[i0]) = o;
            }
        }
    }
}

// ============================================================================
// logits (TF32 mma.sync): logits = g_h @ w2p + b2; fused stats/argmax/counts.
// ============================================================================
__global__ void __launch_bounds__(256) logits_tc(const float* __restrict__ b2)
{
    __shared__ unsigned As[128 * 36];
    __shared__ unsigned Bs[32 * 76];

    const int tid  = threadIdx.x;
    const int lane = tid & 31;
    const int w    = tid >> 5;
    const int g    = lane >> 2;
    const int t    = lane & 3;
    const int row0 = blockIdx.x * 128;

    const int ar = tid >> 3;
    const int af = (tid & 7) * 4;

    int soff[9];
#pragma unroll
    for (int p = 0; p < 9; p++) {
        int i = tid + 256 * p;
        soff[p] = i + 4 * (i / CPAD);
    }

    float acc[9][4];
#pragma unroll
    for (int n = 0; n < 9; n++)
#pragma unroll
        for (int c = 0; c < 4; c++) acc[n][c] = 0.f;

    float4 asg[4];
    unsigned bsg[9];
    const int NT = HDIM / 32;

#pragma unroll
    for (int p = 0; p < 4; p++)
        asg[p] = *reinterpret_cast<const float4*>(&g_h[(size_t)(row0 + ar + 32 * p) * HDIM + af]);
#pragma unroll
    for (int p = 0; p < 9; p++)
        bsg[p] = g_w2p[tid + 256 * p];

    for (int kt = 0; kt < NT; kt++) {
#pragma unroll
        for (int p = 0; p < 4; p++) {
            int rb = (ar + 32 * p) * 36 + af;
            As[rb + 0] = f2tf32(asg[p].x); As[rb + 1] = f2tf32(asg[p].y);
            As[rb + 2] = f2tf32(asg[p].z); As[rb + 3] = f2tf32(asg[p].w);
        }
#pragma unroll
        for (int p = 0; p < 9; p++) Bs[soff[p]] = bsg[p];
        __syncthreads();

        if (kt + 1 < NT) {
            int k0n = (kt + 1) * 32;
#pragma unroll
            for (int p = 0; p < 4; p++)
                asg[p] = *reinterpret_cast<const float4*>(&g_h[(size_t)(row0 + ar + 32 * p) * HDIM + k0n + af]);
#pragma unroll
            for (int p = 0; p < 9; p++)
                bsg[p] = g_w2p[k0n * CPAD + tid + 256 * p];
        }

#pragma unroll
        for (int ks = 0; ks < 4; ks++) {
            int k0 = ks * 8;
            int row = w * 16;
            unsigned a0 = As[(row + g) * 36 + k0 + t];
            unsigned a1 = As[(row + 8 + g) * 36 + k0 + t];
            unsigned a2 = As[(row + g) * 36 + k0 + t + 4];
            unsigned a3 = As[(row + 8 + g) * 36 + k0 + t + 4];
#pragma unroll
            for (int nt = 0; nt < 9; nt++) {
                unsigned b0 = Bs[(k0 + t) * 76 + nt * 8 + g];
                unsigned b1 = Bs[(k0 + t + 4) * 76 + nt * 8 + g];
                mma_tf32(acc[nt], a0, a1, a2, a3, b0, b1);
            }
        }
        __syncthreads();
    }

    float su[9][2];
#pragma unroll
    for (int n = 0; n < 9; n++) { su[n][0] = 0.f; su[n][1] = 0.f; }
    float entL = 0.f;

#pragma unroll
    for (int half = 0; half < 2; half++) {
        int row = row0 + w * 16 + g + 8 * half;
        int ci  = 2 * half;

        float v[9][2];
        float m = -1e30f;
#pragma unroll
        for (int nt = 0; nt < 9; nt++)
#pragma unroll
            for (int j = 0; j < 2; j++) {
                int col = nt * 8 + 2 * t + j;
                v[nt][j] = (col < CDIM) ? acc[nt][ci + j] + b2[col] : -1e30f;
                m = fmaxf(m, v[nt][j]);
            }
        m = fmaxf(m, __shfl_xor_sync(0xffffffffu, m, 1));
        m = fmaxf(m, __shfl_xor_sync(0xffffffffu, m, 2));

        float s = 0.f;
#pragma unroll
        for (int nt = 0; nt < 9; nt++)
#pragma unroll
            for (int j = 0; j < 2; j++) {
                int col = nt * 8 + 2 * t + j;
                if (col < CDIM) s += expf(v[nt][j] - m);
            }
        s += __shfl_xor_sync(0xffffffffu, s, 1);
        s += __shfl_xor_sync(0xffffffffu, s, 2);
        float lse = m + logf(s);

        float bv = -1e30f; int bi = CDIM;
#pragma unroll
        for (int nt = 0; nt < 9; nt++)
#pragma unroll
            for (int j = 0; j < 2; j++) {
                int col = nt * 8 + 2 * t + j;
                if (col < CDIM) {
                    float p = expf(v[nt][j] - lse);
                    entL += p * logf(p + 1e-6f);
                    su[nt][j] += p;
                    g_logits[row * CDIM + col] = v[nt][j];
                    if (v[nt][j] > bv || (v[nt][j] == bv && col < bi)) { bv = v[nt][j]; bi = col; }
                }
            }
#pragma unroll
        for (int o = 1; o <= 2; o <<= 1) {
            float ov = __shfl_xor_sync(0xffffffffu, bv, o);
            int   oi = __shfl_xor_sync(0xffffffffu, bi, o);
            if (ov > bv || (ov == bv && oi < bi)) { bv = ov; bi = oi; }
        }
        if (t == 0) {
            g_lse[row]  = lse;
            g_pred[row] = bi;
            atomicAdd(&g_cnt[bi], 1);
        }
    }

#pragma unroll
    for (int o = 16; o > 0; o >>= 1) entL += __shfl_xor_sync(0xffffffffu, entL, o);
    if (lane == 0) atomicAdd(&g_ent, entL);

#pragma unroll
    for (int o = 4; o <= 16; o <<= 1)
#pragma unroll
        for (int nt = 0; nt < 9; nt++)
#pragma unroll
            for (int j = 0; j < 2; j++)
                su[nt][j] += __shfl_xor_sync(0xffffffffu, su[nt][j], o);
    if (g == 0) {
#pragma unroll
        for (int nt = 0; nt < 9; nt++)
#pragma unroll
            for (int j = 0; j < 2; j++) {
                int col = nt * 8 + 2 * t + j;
                if (col < CDIM) atomicAdd(&g_sump[col], su[nt][j]);
            }
    }
}

// ---------------- per-class segment sum over feat ----------------
__global__ void __launch_bounds__(128) segsum_kernel(const float* __restrict__ feat)
{
    __shared__ float acc[CDIM * 128];
    const int t   = threadIdx.x;
    const int col = blockIdx.x * 128 + t;
    const int rpb = NROWS / 32;
    const int r0  = blockIdx.y * rpb;

    for (int i = t; i < CDIM * 128; i += 128) acc[i] = 0.f;
    __syncthreads();

    for (int i = r0; i < r0 + rpb; i++) {
        int cls = g_pred[i];
        acc[cls * 128 + t] += feat[(size_t)i * DDIM + col];
    }
    __syncthreads();

    for (int c = 0; c < CDIM; c++)
        atomicAdd(&g_csum[c * DDIM + col], acc[c * 128 + t]);
}

// ---------------- finalize centroids (normalized, transposed tf32) ----------------
__global__ void __launch_bounds__(256) centroid_kernel()
{
    __shared__ float red[256];
    const int c = blockIdx.x;
    const int t = threadIdx.x;
    const int cnt = g_cnt[c];
    const float denom = fmaxf((float)cnt, 1.f);

    float ssq = 0.f;
    for (int d = t; d < DDIM; d += 256) {
        float mv = g_csum[c * DDIM + d] / denom;
        ssq += mv * mv;
    }
    red[t] = ssq;
    __syncthreads();
    for (int o = 128; o > 0; o >>= 1) { if (t < o) red[t] += red[t + o]; __syncthreads(); }
    float nrm   = sqrtf(red[0]);
    float scale = (cnt > 0) ? 1.f / (denom * fmaxf(nrm, 1e-12f)) : 0.f;

    for (int d = t; d < DDIM; d += 256)
        g_centTp[d * CPAD + c] = f2tf32(g_csum[c * DDIM + d] * scale);
}

// ============================================================================
// sim (TF32 mma.sync): sim = feat @ centTp; fused argmax + CE.
// ============================================================================
__global__ void __launch_bounds__(256) sim_tc(const float* __restrict__ feat)
{
    __shared__ unsigned As[128 * 36];
    __shared__ unsigned Bs[32 * 76];

    const int tid  = threadIdx.x;
    const int lane = tid & 31;
    const int w    = tid >> 5;
    const int g    = lane >> 2;
    const int t    = lane & 3;
    const int row0 = blockIdx.x * 128;

    const int ar = tid >> 3;
    const int af = (tid & 7) * 4;

    int soff[9];
#pragma unroll
    for (int p = 0; p < 9; p++) {
        int i = tid + 256 * p;
        soff[p] = i + 4 * (i / CPAD);
    }

    float acc[9][4];
#pragma unroll
    for (int n = 0; n < 9; n++)
#pragma unroll
        for (int c = 0; c < 4; c++) acc[n][c] = 0.f;

    float4 asg[4];
    unsigned bsg[9];
    const int NT = DDIM / 32;

#pragma unroll
    for (int p = 0; p < 4; p++)
        asg[p] = *reinterpret_cast<const float4*>(&feat[(size_t)(row0 + ar + 32 * p) * DDIM + af]);
#pragma unroll
    for (int p = 0; p < 9; p++)
        bsg[p] = g_centTp[tid + 256 * p];

    for (int kt = 0; kt < NT; kt++) {
#pragma unroll
        for (int p = 0; p < 4; p++) {
            int rb = (ar + 32 * p) * 36 + af;
            As[rb + 0] = f2tf32(asg[p].x); As[rb + 1] = f2tf32(asg[p].y);
            As[rb + 2] = f2tf32(asg[p].z); As[rb + 3] = f2tf32(asg[p].w);
        }
#pragma unroll
        for (int p = 0; p < 9; p++) Bs[soff[p]] = bsg[p];
        __syncthreads();

        if (kt + 1 < NT) {
            int k0n = (kt + 1) * 32;
#pragma unroll
            for (int p = 0; p < 4; p++)
                asg[p] = *reinterpret_cast<const float4*>(&feat[(size_t)(row0 + ar + 32 * p) * DDIM + k0n + af]);
#pragma unroll
            for (int p = 0; p < 9; p++)
                bsg[p] = g_centTp[k0n * CPAD + tid + 256 * p];
        }

#pragma unroll
        for (int ks = 0; ks < 4; ks++) {
            int k0 = ks * 8;
            int row = w * 16;
            unsigned a0 = As[(row + g) * 36 + k0 + t];
            unsigned a1 = As[(row + 8 + g) * 36 + k0 + t];
            unsigned a2 = As[(row + g) * 36 + k0 + t + 4];
            unsigned a3 = As[(row + 8 + g) * 36 + k0 + t + 4];
#pragma unroll
            for (int nt = 0; nt < 9; nt++) {
                unsigned b0 = Bs[(k0 + t) * 76 + nt * 8 + g];
                unsigned b1 = Bs[(k0 + t + 4) * 76 + nt * 8 + g];
                mma_tf32(acc[nt], a0, a1, a2, a3, b0, b1);
            }
        }
        __syncthreads();
    }

    float ceL = 0.f;
#pragma unroll
    for (int half = 0; half < 2; half++) {
        int row = row0 + w * 16 + g + 8 * half;
        int ci  = 2 * half;

        float bv = -1e30f; int bi = CDIM;
#pragma unroll
        for (int nt = 0; nt < 9; nt++)
#pragma unroll
            for (int j = 0; j < 2; j++) {
                int col = nt * 8 + 2 * t + j;
                if (col < CDIM) {
                    float vv = acc[nt][ci + j];
                    if (vv > bv || (vv == bv && col < bi)) { bv = vv; bi = col; }
                }
            }
#pragma unroll
        for (int o = 1; o <= 2; o <<= 1) {
            float ov = __shfl_xor_sync(0xffffffffu, bv, o);
            int   oi = __shfl_xor_sync(0xffffffffu, bi, o);
            if (ov > bv || (ov == bv && oi < bi)) { bv = ov; bi = oi; }
        }
        if (t == 0)
            ceL += g_lse[row] - g_logits[row * CDIM + bi];
    }
#pragma unroll
    for (int o = 16; o > 0; o >>= 1) ceL += __shfl_xor_sync(0xffffffffu, ceL, o);
    if (lane == 0) atomicAdd(&g_ce, ceL);
}

// ---------------- final scalar ----------------
__global__ void finalize_kernel(float* __restrict__ out)
{
    __shared__ float red[128];
    int t = threadIdx.x;
    float v = 0.f;
    if (t < CDIM) {
        float mp = g_sump[t] * (1.f / NROWS);
        v = mp * logf(mp + 1e-6f);
    }
    red[t] = v;
    __syncthreads();
    for (int o = 64; o > 0; o >>= 1) { if (t < o) red[t] += red[t + o]; __syncthreads(); }
    if (t == 0) {
        float entropy = -g_ent * (1.f / NROWS);
        float ce      =  g_ce  * (1.f / NROWS);
        out[0] = entropy + red[0] + 0.3f * ce;
    }
}

// ---------------- launch ----------------
extern "C" void kernel_launch(void* const* d_in, const int* in_sizes, int n_in,
                              void* d_out, int out_size)
{
    const float* feat = (const float*)d_in[0];
    const float* w1   = (const float*)d_in[1];
    const float* b1   = (const float*)d_in[2];
    const float* w2   = (const float*)d_in[3];
    const float* b2   = (const float*)d_in[4];
    float* out = (float*)d_out;

    cudaFuncSetAttribute(gemm1_fp16, cudaFuncAttributeMaxDynamicSharedMemorySize, G1_SMEM);

    zero_kernel<<<(DDIM * CPAD + 255) / 256, 256>>>();
    pad_w2_kernel<<<(HDIM * CPAD + 255) / 256, 256>>>(w2);
    feat16_kernel<<<NROWS * DDIM / (256 * 8), 256>>>(feat);
    w1t_kernel<<<dim3(DDIM / 32, HDIM / 32), dim3(32, 8)>>>(w1);
    gemm1_fp16<<<dim3(HDIM / 128, NROWS / 128), 256, G1_SMEM>>>(b1);
    logits_tc<<<NROWS / 128, 256>>>(b2);
    segsum_kernel<<<dim3(DDIM / 128, 32), 128>>>(feat);
    centroid_kernel<<<CDIM, 256>>>();
    sim_tc<<<NROWS / 128, 256>>>(feat);
    finalize_kernel<<<1, 128>>>(out);
}

// round 8
// speedup vs baseline: 5.9455x; 1.2519x over previous
#include <cuda_runtime.h>
#include <cuda_fp16.h>
#include <math.h>
#include <stdint.h>

#define NROWS 16384
#define DDIM  2048
#define HDIM  512
#define CDIM  65
#define KPAIRS (DDIM / 2)
#define BPADR 96     // padded B rows for ldmatrix groups of 32

// ---------------- scratch (device globals; no allocation) ----------------
__device__ __half        g_h16[NROWS * HDIM];      // post-dropout hidden (fp16)
__device__ __half        g_feat16[NROWS * DDIM];   // feat converted to fp16
__device__ float         g_logits[NROWS * CDIM];
__device__ float         g_lse[NROWS];
__device__ int           g_pred[NROWS];
__device__ float         g_sump[CDIM];
__device__ float         g_ent;
__device__ float         g_ce;
__device__ float         g_csum[CDIM * DDIM];
__device__ int           g_cnt[CDIM];
__device__ unsigned      g_w1Th[HDIM * KPAIRS];    // half2 pairs, [n][k]
__device__ __half        g_w2T16[BPADR * HDIM];    // [n][k] fp16, rows>=CDIM zero
__device__ __half        g_cent16[BPADR * DDIM];   // [c][d] fp16 centroids

// ---------------- helpers ----------------
__device__ __forceinline__ unsigned pack_h2(float a, float b)
{
    __half2 h = __floats2half2_rn(a, b);
    return *reinterpret_cast<unsigned*>(&h);
}

__device__ __forceinline__ unsigned smem_u32(const void* p)
{
    unsigned a;
    asm("{ .reg .u64 t; cvta.to.shared.u64 t, %1; cvt.u32.u64 %0, t; }" : "=r"(a) : "l"(p));
    return a;
}

__device__ __forceinline__ void mma_f16(float c[4],
                                        unsigned a0, unsigned a1, unsigned a2, unsigned a3,
                                        unsigned b0, unsigned b1)
{
    asm volatile(
        "mma.sync.aligned.m16n8k16.row.col.f32.f16.f16.f32 "
        "{%0,%1,%2,%3}, {%4,%5,%6,%7}, {%8,%9}, {%0,%1,%2,%3};"
        : "+f"(c[0]), "+f"(c[1]), "+f"(c[2]), "+f"(c[3])
        : "r"(a0), "r"(a1), "r"(a2), "r"(a3), "r"(b0), "r"(b1));
}

__device__ __forceinline__ void ldsm_x4(unsigned& r0, unsigned& r1, unsigned& r2, unsigned& r3,
                                        unsigned saddr)
{
    asm volatile("ldmatrix.sync.aligned.m8n8.x4.shared.b16 {%0,%1,%2,%3}, [%4];"
                 : "=r"(r0), "=r"(r1), "=r"(r2), "=r"(r3) : "r"(saddr));
}

#define CP_ASYNC16(dst, src) \
    asm volatile("cp.async.cg.shared.global [%0], [%1], 16;" :: "r"(dst), "l"(src))
#define CP_COMMIT() asm volatile("cp.async.commit_group;")
#define CP_WAIT(n)  asm volatile("cp.async.wait_group %0;" :: "n"(n))

// ---------------- threefry2x32 (JAX partitionable, key = (0, 42)) ----------------
__device__ __forceinline__ void threefry2x32_42(unsigned c0, unsigned c1,
                                                unsigned& o0, unsigned& o1)
{
    const unsigned ks0 = 0u;
    const unsigned ks1 = 42u;
    const unsigned ks2 = 0x1BD11BDAu ^ 0u ^ 42u;
    unsigned x0 = c0 + ks0;
    unsigned x1 = c1 + ks1;
#define TF_ROUND(r) { x0 += x1; x1 = (x1 << (r)) | (x1 >> (32 - (r))); x1 ^= x0; }
    TF_ROUND(13) TF_ROUND(15) TF_ROUND(26) TF_ROUND(6)
    x0 += ks1; x1 += ks2 + 1u;
    TF_ROUND(17) TF_ROUND(29) TF_ROUND(16) TF_ROUND(24)
    x0 += ks2; x1 += ks0 + 2u;
    TF_ROUND(13) TF_ROUND(15) TF_ROUND(26) TF_ROUND(6)
    x0 += ks0; x1 += ks1 + 3u;
    TF_ROUND(17) TF_ROUND(29) TF_ROUND(16) TF_ROUND(24)
    x0 += ks1; x1 += ks2 + 4u;
    TF_ROUND(13) TF_ROUND(15) TF_ROUND(26) TF_ROUND(6)
    x0 += ks2; x1 += ks0 + 5u;
#undef TF_ROUND
    o0 = x0; o1 = x1;
}

__device__ __forceinline__ bool keep_bit(unsigned idx)
{
    unsigned a, b;
    threefry2x32_42(0u, idx, a, b);
    return (b >> 31) == 0u;
}

__global__ void zero_kernel()
{
    int i = blockIdx.x * blockDim.x + threadIdx.x;
    if (i < CDIM * DDIM) g_csum[i] = 0.f;
    if (i < CDIM) { g_sump[i] = 0.f; g_cnt[i] = 0; }
    if (i == 0) { g_ent = 0.f; g_ce = 0.f; }
}

// w2 [512][65] -> g_w2T16 [96][512], rows >= 65 zero
__global__ void __launch_bounds__(256) w2t16_kernel(const float* __restrict__ w2)
{
    int i = blockIdx.x * blockDim.x + threadIdx.x;
    if (i >= BPADR * HDIM) return;
    int n = i / HDIM, k = i - n * HDIM;
    g_w2T16[i] = (n < CDIM) ? __float2half_rn(w2[k * CDIM + n]) : __float2half_rn(0.f);
}

// feat fp32 -> fp16, 8 elements per thread
__global__ void __launch_bounds__(256) feat16_kernel(const float* __restrict__ feat)
{
    size_t i = ((size_t)blockIdx.x * 256 + threadIdx.x) * 8;
    float4 v0 = *reinterpret_cast<const float4*>(feat + i);
    float4 v1 = *reinterpret_cast<const float4*>(feat + i + 4);
    uint4 o;
    o.x = pack_h2(v0.x, v0.y);
    o.y = pack_h2(v0.z, v0.w);
    o.z = pack_h2(v1.x, v1.y);
    o.w = pack_h2(v1.z, v1.w);
    *reinterpret_cast<uint4*>(&g_feat16[i]) = o;
}

// w1 [K=2048][N=512] -> g_w1Th [N][K] half pairs (tiled transpose)
__global__ void __launch_bounds__(256) w1t_kernel(const float* __restrict__ w1)
{
    __shared__ float t[32][33];
    const int k0 = blockIdx.x * 32, n0 = blockIdx.y * 32;
    const int x = threadIdx.x, y = threadIdx.y;
#pragma unroll
    for (int i = y; i < 32; i += 8) t[i][x] = w1[(size_t)(k0 + i) * HDIM + n0 + x];
    __syncthreads();
#pragma unroll
    for (int i = y; i < 16; i += 8)
        g_w1Th[(size_t)(n0 + x) * KPAIRS + k0 / 2 + i] = pack_h2(t[2 * i][x], t[2 * i + 1][x]);
}

// ============================================================================
// GEMM1 (fp16, cp.async + ldmatrix): g_h16 = dropout(relu(feat @ w1 + b1))
// CTA 128x128, BK=64, 256 threads, 8 warps of 64x32, 2-stage pipeline.
// ============================================================================
#define G1_SMEM (2 * 32768)

__global__ void __launch_bounds__(256) gemm1_fp16(const float* __restrict__ bias)
{
    extern __shared__ __align__(1024) char dsm[];
    __shared__ float sb[128];

    const unsigned sbase = smem_u32(dsm);
    const int tid  = threadIdx.x;
    const int lane = tid & 31;
    const int w    = tid >> 5;
    const int g    = lane >> 2;
    const int t    = lane & 3;
    const int wm   = w & 1;
    const int wn   = w >> 1;
    const int brow = blockIdx.y * 128;
    const int bcol = blockIdx.x * 128;

    if (tid < 128) sb[tid] = bias[bcol + tid];

    const int NT = DDIM / 64;           // 32
    const int cr = tid >> 3;
    const int cc = tid & 7;

    auto issue_copy = [&](int kt) {
        const unsigned aoff = (kt & 1) * 32768u;
        const unsigned boff = aoff + 16384u;
        const __half* Ag = &g_feat16[(size_t)brow * DDIM + kt * 64];
        const unsigned* Bg = &g_w1Th[(size_t)bcol * KPAIRS + kt * 32];
#pragma unroll
        for (int i = 0; i < 4; i++) {
            int r = cr + 32 * i;
            unsigned dsw = (unsigned)((cc ^ (r & 7)) << 4);
            CP_ASYNC16(sbase + aoff + r * 128 + dsw, Ag + (size_t)r * DDIM + cc * 8);
            CP_ASYNC16(sbase + boff + r * 128 + dsw, Bg + (size_t)r * KPAIRS + cc * 4);
        }
        CP_COMMIT();
    };

    float acc[4][4][4];
#pragma unroll
    for (int i = 0; i < 4; i++)
#pragma unroll
        for (int j = 0; j < 4; j++)
#pragma unroll
            for (int c = 0; c < 4; c++) acc[i][j][c] = 0.f;

    issue_copy(0);

    for (int kt = 0; kt < NT; kt++) {
        if (kt + 1 < NT) { issue_copy(kt + 1); CP_WAIT(1); }
        else             { CP_WAIT(0); }
        __syncthreads();

        const unsigned aoff = (kt & 1) * 32768u;
        const unsigned boff = aoff + 16384u;

        const int bn = wn * 32 + lane;
        const unsigned bline = sbase + boff + bn * 128;
        const int arl = (lane & 15);
        const int ach = (lane >> 4);

#pragma unroll
        for (int ks = 0; ks < 4; ks++) {
            unsigned b0[4], b1[4];
            {
                int c0 = (2 * ks) ^ (bn & 7);
                int c1 = (2 * ks + 1) ^ (bn & 7);
                ldsm_x4(b0[0], b0[1], b0[2], b0[3], bline + (c0 << 4));
                ldsm_x4(b1[0], b1[1], b1[2], b1[3], bline + (c1 << 4));
            }
#pragma unroll
            for (int mt = 0; mt < 4; mt++) {
                int row = wm * 64 + mt * 16 + arl;
                int ch  = (2 * ks + ach) ^ (row & 7);
                unsigned a0, a1, a2, a3;
                ldsm_x4(a0, a1, a2, a3, sbase + aoff + row * 128 + (ch << 4));
#pragma unroll
                for (int nt = 0; nt < 4; nt++)
                    mma_f16(acc[mt][nt], a0, a1, a2, a3, b0[nt], b1[nt]);
            }
        }
        __syncthreads();
    }

    // epilogue: bias + relu + threefry dropout -> g_h16 (fp16)
#pragma unroll
    for (int mt = 0; mt < 4; mt++) {
#pragma unroll
        for (int h = 0; h < 2; h++) {
            int row = brow + wm * 64 + mt * 16 + g + 8 * h;
#pragma unroll
            for (int nt = 0; nt < 4; nt++) {
                int colL = wn * 32 + nt * 8 + 2 * t;
                unsigned i0 = (unsigned)(row * HDIM + bcol + colL);
                float v0 = fmaxf(acc[mt][nt][2 * h + 0] + sb[colL], 0.f);
                float v1 = fmaxf(acc[mt][nt][2 * h + 1] + sb[colL + 1], 0.f);
                unsigned o = pack_h2(keep_bit(i0)     ? (v0 + v0) : 0.f,
                                     keep_bit(i0 + 1) ? (v1 + v1) : 0.f);
                *reinterpret_cast<unsigned*>(&g_h16[i0]) = o;
            }
        }
    }
}

// ============================================================================
// Skinny fp16 GEMM skeleton: 128 rows x 80 cols (10 n8-tiles), B padded 96 rows.
// 256 threads, 8 warps x 16 rows, BK=64, 2-stage cp.async pipeline.
// Stage layout: A 16KB | B 12KB ; stage stride 28672; total 57344.
// ============================================================================
#define SK_SMEM 57344

// ---- logits: A = g_h16 [N][512], B = g_w2T16 ----
__global__ void __launch_bounds__(256) logits_f16(const float* __restrict__ b2)
{
    extern __shared__ __align__(1024) char dsm[];
    const unsigned sbase = smem_u32(dsm);
    const int tid  = threadIdx.x;
    const int lane = tid & 31;
    const int w    = tid >> 5;
    const int g    = lane >> 2;
    const int t    = lane & 3;
    const int row0 = blockIdx.x * 128;
    const int cr   = tid >> 3;
    const int cc   = tid & 7;

    auto issue_copy = [&](int kt) {
        const unsigned aoff = (kt & 1) * 28672u;
        const unsigned boff = aoff + 16384u;
        const __half* Ag = &g_h16[(size_t)row0 * HDIM + kt * 64];
        const __half* Bg = &g_w2T16[kt * 64];
#pragma unroll
        for (int i = 0; i < 4; i++) {
            int r = cr + 32 * i;
            unsigned dsw = (unsigned)((cc ^ (r & 7)) << 4);
            CP_ASYNC16(sbase + aoff + r * 128 + dsw, Ag + (size_t)r * HDIM + cc * 8);
        }
#pragma unroll
        for (int i = 0; i < 3; i++) {
            int q = tid + 256 * i;
            int r = q >> 3, c = q & 7;
            unsigned dsw = (unsigned)((c ^ (r & 7)) << 4);
            CP_ASYNC16(sbase + boff + r * 128 + dsw, Bg + (size_t)r * HDIM + c * 8);
        }
        CP_COMMIT();
    };

    float acc[10][4];
#pragma unroll
    for (int n = 0; n < 10; n++)
#pragma unroll
        for (int c = 0; c < 4; c++) acc[n][c] = 0.f;

    issue_copy(0);
    const int NT = HDIM / 64;   // 8
    for (int kt = 0; kt < NT; kt++) {
        if (kt + 1 < NT) { issue_copy(kt + 1); CP_WAIT(1); }
        else             { CP_WAIT(0); }
        __syncthreads();

        const unsigned aoff = (kt & 1) * 28672u;
        const unsigned boff = aoff + 16384u;
        const int arl = lane & 15;
        const int ach = lane >> 4;

#pragma unroll
        for (int ks = 0; ks < 4; ks++) {
            unsigned b0[12], b1[12];
#pragma unroll
            for (int gr = 0; gr < 3; gr++) {
                int bn = gr * 32 + lane;
                unsigned bline = sbase + boff + bn * 128;
                int c0 = (2 * ks) ^ (bn & 7);
                int c1 = (2 * ks + 1) ^ (bn & 7);
                ldsm_x4(b0[gr*4+0], b0[gr*4+1], b0[gr*4+2], b0[gr*4+3], bline + (c0 << 4));
                ldsm_x4(b1[gr*4+0], b1[gr*4+1], b1[gr*4+2], b1[gr*4+3], bline + (c1 << 4));
            }
            int row = w * 16 + arl;
            int ch  = (2 * ks + ach) ^ (row & 7);
            unsigned a0, a1, a2, a3;
            ldsm_x4(a0, a1, a2, a3, sbase + aoff + row * 128 + (ch << 4));
#pragma unroll
            for (int nt = 0; nt < 10; nt++)
                mma_f16(acc[nt], a0, a1, a2, a3, b0[nt], b1[nt]);
        }
        __syncthreads();
    }

    // ---- epilogue: softmax stats / argmax / counts ----
    float su[10][2];
#pragma unroll
    for (int n = 0; n < 10; n++) { su[n][0] = 0.f; su[n][1] = 0.f; }
    float entL = 0.f;

#pragma unroll
    for (int half = 0; half < 2; half++) {
        int row = row0 + w * 16 + g + 8 * half;
        int ci  = 2 * half;

        float v[10][2];
        float m = -1e30f;
#pragma unroll
        for (int nt = 0; nt < 10; nt++)
#pragma unroll
            for (int j = 0; j < 2; j++) {
                int col = nt * 8 + 2 * t + j;
                v[nt][j] = (col < CDIM) ? acc[nt][ci + j] + b2[col] : -1e30f;
                m = fmaxf(m, v[nt][j]);
            }
        m = fmaxf(m, __shfl_xor_sync(0xffffffffu, m, 1));
        m = fmaxf(m, __shfl_xor_sync(0xffffffffu, m, 2));

        float s = 0.f;
#pragma unroll
        for (int nt = 0; nt < 10; nt++)
#pragma unroll
            for (int j = 0; j < 2; j++) {
                int col = nt * 8 + 2 * t + j;
                if (col < CDIM) s += expf(v[nt][j] - m);
            }
        s += __shfl_xor_sync(0xffffffffu, s, 1);
        s += __shfl_xor_sync(0xffffffffu, s, 2);
        float lse = m + logf(s);

        float bv = -1e30f; int bi = CDIM;
#pragma unroll
        for (int nt = 0; nt < 10; nt++)
#pragma unroll
            for (int j = 0; j < 2; j++) {
                int col = nt * 8 + 2 * t + j;
                if (col < CDIM) {
                    float p = expf(v[nt][j] - lse);
                    entL += p * logf(p + 1e-6f);
                    su[nt][j] += p;
                    g_logits[row * CDIM + col] = v[nt][j];
                    if (v[nt][j] > bv || (v[nt][j] == bv && col < bi)) { bv = v[nt][j]; bi = col; }
                }
            }
#pragma unroll
        for (int o = 1; o <= 2; o <<= 1) {
            float ov = __shfl_xor_sync(0xffffffffu, bv, o);
            int   oi = __shfl_xor_sync(0xffffffffu, bi, o);
            if (ov > bv || (ov == bv && oi < bi)) { bv = ov; bi = oi; }
        }
        if (t == 0) {
            g_lse[row]  = lse;
            g_pred[row] = bi;
            atomicAdd(&g_cnt[bi], 1);
        }
    }

#pragma unroll
    for (int o = 16; o > 0; o >>= 1) entL += __shfl_xor_sync(0xffffffffu, entL, o);
    if (lane == 0) atomicAdd(&g_ent, entL);

#pragma unroll
    for (int o = 4; o <= 16; o <<= 1)
#pragma unroll
        for (int nt = 0; nt < 10; nt++)
#pragma unroll
            for (int j = 0; j < 2; j++)
                su[nt][j] += __shfl_xor_sync(0xffffffffu, su[nt][j], o);
    if (g == 0) {
#pragma unroll
        for (int nt = 0; nt < 10; nt++)
#pragma unroll
            for (int j = 0; j < 2; j++) {
                int col = nt * 8 + 2 * t + j;
                if (col < CDIM) atomicAdd(&g_sump[col], su[nt][j]);
            }
    }
}

// ---- per-class segment sum over feat (fp16 source, half2 per thread) ----
#define SEG_SMEM (CDIM * 128 * 8)
__global__ void __launch_bounds__(128) segsum_f16()
{
    extern __shared__ __align__(16) float2 sacc[];   // [CDIM][128]
    const int t    = threadIdx.x;
    const int col2 = blockIdx.x * 128 + t;           // half2 column index
    const int rpb  = NROWS / 32;
    const int r0   = blockIdx.y * rpb;

    for (int i = t; i < CDIM * 128; i += 128) sacc[i] = make_float2(0.f, 0.f);
    __syncthreads();

    const unsigned* f2 = reinterpret_cast<const unsigned*>(g_feat16);
    for (int i = r0; i < r0 + rpb; i++) {
        int cls = g_pred[i];
        unsigned u = f2[(size_t)i * (DDIM / 2) + col2];
        __half2 h = *reinterpret_cast<__half2*>(&u);
        float2 v = __half22float2(h);
        float2& a = sacc[cls * 128 + t];
        a.x += v.x; a.y += v.y;
    }
    __syncthreads();

    for (int c = 0; c < CDIM; c++) {
        float2 a = sacc[c * 128 + t];
        atomicAdd(&g_csum[c * DDIM + col2 * 2], a.x);
        atomicAdd(&g_csum[c * DDIM + col2 * 2 + 1], a.y);
    }
}

// ---- finalize centroids (normalized), K-major fp16; grid = 96 ----
__global__ void __launch_bounds__(256) centroid_f16()
{
    __shared__ float red[256];
    const int c = blockIdx.x;
    const int t = threadIdx.x;
    if (c >= CDIM) {
        for (int d = t; d < DDIM; d += 256) g_cent16[(size_t)c * DDIM + d] = __float2half_rn(0.f);
        return;
    }
    const int cnt = g_cnt[c];
    const float denom = fmaxf((float)cnt, 1.f);

    float ssq = 0.f;
    for (int d = t; d < DDIM; d += 256) {
        float mv = g_csum[c * DDIM + d] / denom;
        ssq += mv * mv;
    }
    red[t] = ssq;
    __syncthreads();
    for (int o = 128; o > 0; o >>= 1) { if (t < o) red[t] += red[t + o]; __syncthreads(); }
    float nrm   = sqrtf(red[0]);
    float scale = (cnt > 0) ? 1.f / (denom * fmaxf(nrm, 1e-12f)) : 0.f;

    for (int d = t; d < DDIM; d += 256)
        g_cent16[(size_t)c * DDIM + d] = __float2half_rn(g_csum[c * DDIM + d] * scale);
}

// ---- sim: A = g_feat16 [N][2048], B = g_cent16 ; fused argmax + CE ----
__global__ void __launch_bounds__(256) sim_f16()
{
    extern __shared__ __align__(1024) char dsm[];
    const unsigned sbase = smem_u32(dsm);
    const int tid  = threadIdx.x;
    const int lane = tid & 31;
    const int w    = tid >> 5;
    const int t    = lane & 3;
    const int row0 = blockIdx.x * 128;
    const int cr   = tid >> 3;
    const int cc   = tid & 7;

    auto issue_copy = [&](int kt) {
        const unsigned aoff = (kt & 1) * 28672u;
        const unsigned boff = aoff + 16384u;
        const __half* Ag = &g_feat16[(size_t)row0 * DDIM + kt * 64];
        const __half* Bg = &g_cent16[kt * 64];
#pragma unroll
        for (int i = 0; i < 4; i++) {
            int r = cr + 32 * i;
            unsigned dsw = (unsigned)((cc ^ (r & 7)) << 4);
            CP_ASYNC16(sbase + aoff + r * 128 + dsw, Ag + (size_t)r * DDIM + cc * 8);
        }
#pragma unroll
        for (int i = 0; i < 3; i++) {
            int q = tid + 256 * i;
            int r = q >> 3, c = q & 7;
            unsigned dsw = (unsigned)((c ^ (r & 7)) << 4);
            CP_ASYNC16(sbase + boff + r * 128 + dsw, Bg + (size_t)r * DDIM + c * 8);
        }
        CP_COMMIT();
    };

    float acc[10][4];
#pragma unroll
    for (int n = 0; n < 10; n++)
#pragma unroll
        for (int c = 0; c < 4; c++) acc[n][c] = 0.f;

    issue_copy(0);
    const int NT = DDIM / 64;   // 32
    for (int kt = 0; kt < NT; kt++) {
        if (kt + 1 < NT) { issue_copy(kt + 1); CP_WAIT(1); }
        else             { CP_WAIT(0); }
        __syncthreads();

        const unsigned aoff = (kt & 1) * 28672u;
        const unsigned boff = aoff + 16384u;
        const int arl = lane & 15;
        const int ach = lane >> 4;

#pragma unroll
        for (int ks = 0; ks < 4; ks++) {
            unsigned b0[12], b1[12];
#pragma unroll
            for (int gr = 0; gr < 3; gr++) {
                int bn = gr * 32 + lane;
                unsigned bline = sbase + boff + bn * 128;
                int c0 = (2 * ks) ^ (bn & 7);
                int c1 = (2 * ks + 1) ^ (bn & 7);
                ldsm_x4(b0[gr*4+0], b0[gr*4+1], b0[gr*4+2], b0[gr*4+3], bline + (c0 << 4));
                ldsm_x4(b1[gr*4+0], b1[gr*4+1], b1[gr*4+2], b1[gr*4+3], bline + (c1 << 4));
            }
            int row = w * 16 + arl;
            int ch  = (2 * ks + ach) ^ (row & 7);
            unsigned a0, a1, a2, a3;
            ldsm_x4(a0, a1, a2, a3, sbase + aoff + row * 128 + (ch << 4));
#pragma unroll
            for (int nt = 0; nt < 10; nt++)
                mma_f16(acc[nt], a0, a1, a2, a3, b0[nt], b1[nt]);
        }
        __syncthreads();
    }

    const int g = lane >> 2;
    float ceL = 0.f;
#pragma unroll
    for (int half = 0; half < 2; half++) {
        int row = row0 + w * 16 + g + 8 * half;
        int ci  = 2 * half;

        float bv = -1e30f; int bi = CDIM;
#pragma unroll
        for (int nt = 0; nt < 10; nt++)
#pragma unroll
            for (int j = 0; j < 2; j++) {
                int col = nt * 8 + 2 * t + j;
                if (col < CDIM) {
                    float vv = acc[nt][ci + j];
                    if (vv > bv || (vv == bv && col < bi)) { bv = vv; bi = col; }
                }
            }
#pragma unroll
        for (int o = 1; o <= 2; o <<= 1) {
            float ov = __shfl_xor_sync(0xffffffffu, bv, o);
            int   oi = __shfl_xor_sync(0xffffffffu, bi, o);
            if (ov > bv || (ov == bv && oi < bi)) { bv = ov; bi = oi; }
        }
        if (t == 0)
            ceL += g_lse[row] - g_logits[row * CDIM + bi];
    }
#pragma unroll
    for (int o = 16; o > 0; o >>= 1) ceL += __shfl_xor_sync(0xffffffffu, ceL, o);
    if (lane == 0) atomicAdd(&g_ce, ceL);
}

// ---------------- final scalar ----------------
__global__ void finalize_kernel(float* __restrict__ out)
{
    __shared__ float red[128];
    int t = threadIdx.x;
    float v = 0.f;
    if (t < CDIM) {
        float mp = g_sump[t] * (1.f / NROWS);
        v = mp * logf(mp + 1e-6f);
    }
    red[t] = v;
    __syncthreads();
    for (int o = 64; o > 0; o >>= 1) { if (t < o) red[t] += red[t + o]; __syncthreads(); }
    if (t == 0) {
        float entropy = -g_ent * (1.f / NROWS);
        float ce      =  g_ce  * (1.f / NROWS);
        out[0] = entropy + red[0] + 0.3f * ce;
    }
}

// ---------------- launch ----------------
extern "C" void kernel_launch(void* const* d_in, const int* in_sizes, int n_in,
                              void* d_out, int out_size)
{
    const float* feat = (const float*)d_in[0];
    const float* w1   = (const float*)d_in[1];
    const float* b1   = (const float*)d_in[2];
    const float* w2   = (const float*)d_in[3];
    const float* b2   = (const float*)d_in[4];
    float* out = (float*)d_out;

    cudaFuncSetAttribute(gemm1_fp16, cudaFuncAttributeMaxDynamicSharedMemorySize, G1_SMEM);
    cudaFuncSetAttribute(logits_f16, cudaFuncAttributeMaxDynamicSharedMemorySize, SK_SMEM);
    cudaFuncSetAttribute(sim_f16,    cudaFuncAttributeMaxDynamicSharedMemorySize, SK_SMEM);
    cudaFuncSetAttribute(segsum_f16, cudaFuncAttributeMaxDynamicSharedMemorySize, SEG_SMEM);

    zero_kernel<<<(CDIM * DDIM + 255) / 256, 256>>>();
    w2t16_kernel<<<(BPADR * HDIM + 255) / 256, 256>>>(w2);
    feat16_kernel<<<NROWS * DDIM / (256 * 8), 256>>>(feat);
    w1t_kernel<<<dim3(DDIM / 32, HDIM / 32), dim3(32, 8)>>>(w1);
    gemm1_fp16<<<dim3(HDIM / 128, NROWS / 128), 256, G1_SMEM>>>(b1);
    logits_f16<<<NROWS / 128, 256, SK_SMEM>>>(b2);
    segsum_f16<<<dim3(DDIM / 256, 32), 128, SEG_SMEM>>>();
    centroid_f16<<<BPADR, 256>>>();
    sim_f16<<<NROWS / 128, 256, SK_SMEM>>>();
    finalize_kernel<<<1, 128>>>(out);
}